// round 3
// baseline (speedup 1.0000x reference)
#include <cuda_runtime.h>
#include <cfloat>
#include <cstddef>

#define HID   768
#define INTER 3072
#define NH    12
#define DH    64
#define NTOK  16384
#define WIN   256
#define CH    256
#define MIDW  (3*HID + INTER)   // 5376
#define QKVW  (3*HID)           // 2304
#define COMBW (HID + INTER)     // 3840
#define NCHUNK (NTOK / CH)      // 64

// Scratch (device globals: allocation inside kernel_launch is forbidden)
__device__ float g_xn  [(size_t)NTOK * HID];    //  50 MB
__device__ float g_qkv [(size_t)NTOK * QKVW];   // 151 MB
__device__ float g_comb[(size_t)NTOK * COMBW];  // 252 MB

// ---------------------------------------------------------------- GELU (tanh approx = jax default)
__device__ __forceinline__ float gelu_f(float x) {
    float x3 = x * x * x;
    return 0.5f * x * (1.0f + tanhf(0.7978845608028654f * (x + 0.044715f * x3)));
}

// ---------------------------------------------------------------- LayerNorm
__global__ void ln_kernel(const float* __restrict__ x,
                          const float* __restrict__ gam,
                          const float* __restrict__ bet)
{
    int row = blockIdx.x;
    int t   = threadIdx.x;          // 256 threads, 3 elems each
    const float* xr = x + (size_t)row * HID;
    float v0 = xr[t], v1 = xr[t + 256], v2 = xr[t + 512];
    float s  = v0 + v1 + v2;
    float s2 = v0*v0 + v1*v1 + v2*v2;
    #pragma unroll
    for (int o = 16; o > 0; o >>= 1) {
        s  += __shfl_xor_sync(0xffffffffu, s,  o);
        s2 += __shfl_xor_sync(0xffffffffu, s2, o);
    }
    __shared__ float red0[8], red1[8];
    __shared__ float stat[2];
    int w = t >> 5, l = t & 31;
    if (l == 0) { red0[w] = s; red1[w] = s2; }
    __syncthreads();
    if (t == 0) {
        float ts = 0.f, ts2 = 0.f;
        #pragma unroll
        for (int i = 0; i < 8; i++) { ts += red0[i]; ts2 += red1[i]; }
        float mu  = ts * (1.0f / HID);
        float var = ts2 * (1.0f / HID) - mu * mu;
        stat[0] = mu;
        stat[1] = rsqrtf(var + 1e-5f);
    }
    __syncthreads();
    float mu = stat[0], inv = stat[1];
    float* o = g_xn + (size_t)row * HID;
    o[t]       = (v0 - mu) * inv * gam[t]       + bet[t];
    o[t + 256] = (v1 - mu) * inv * gam[t + 256] + bet[t + 256];
    o[t + 512] = (v2 - mu) * inv * gam[t + 512] + bet[t + 512];
}

// ---------------------------------------------------------------- SGEMM
// C[M,N] = epi( A[M,K](lda) @ B[K,N](ldb) + bias[N] [+ R[M,N](ldc)] )
// epi: 0 = none, 1 = gelu.  128x128 tile, BK=16, 256 threads, 8x8 per thread,
// register-prefetch double buffering. Requires M%128==0, N%128==0, K%16==0.
__global__ __launch_bounds__(256, 2)
void sgemm_kernel(const float* __restrict__ A, int lda,
                  const float* __restrict__ B, int ldb,
                  const float* __restrict__ bias,
                  const float* __restrict__ R,
                  float* __restrict__ C, int ldc,
                  int M, int N, int K, int epi)
{
    __shared__ __align__(16) float As[16][128];
    __shared__ __align__(16) float Bs[16][128];

    int t  = threadIdx.x;
    int bm = blockIdx.y * 128, bn = blockIdx.x * 128;
    int tm = (t >> 4) * 4, tn = (t & 15) * 4;

    float acc[8][8];
    #pragma unroll
    for (int i = 0; i < 8; i++)
        #pragma unroll
        for (int j = 0; j < 8; j++) acc[i][j] = 0.f;

    int arow  = t >> 1;            // 0..127
    int acol4 = (t & 1) * 2;       // float4 index 0/2 (loads acol4, acol4+1)
    int brow  = t >> 4;            // 0..15
    int bcol4 = (t & 15) * 2;      // float4 index, loads bcol4, bcol4+1

    const float* Aptr = A + (size_t)(bm + arow) * lda + acol4 * 4;
    const float* Bptr = B + (size_t)brow * ldb + bn + bcol4 * 4;

    float4 na0 = *(const float4*)(Aptr);
    float4 na1 = *(const float4*)(Aptr + 4);
    float4 nb0 = *(const float4*)(Bptr);
    float4 nb1 = *(const float4*)(Bptr + 4);

    for (int k0 = 0; k0 < K; k0 += 16) {
        int ka = acol4 * 4;
        As[ka + 0][arow] = na0.x; As[ka + 1][arow] = na0.y;
        As[ka + 2][arow] = na0.z; As[ka + 3][arow] = na0.w;
        As[ka + 4][arow] = na1.x; As[ka + 5][arow] = na1.y;
        As[ka + 6][arow] = na1.z; As[ka + 7][arow] = na1.w;
        *(float4*)&Bs[brow][bcol4 * 4]     = nb0;
        *(float4*)&Bs[brow][bcol4 * 4 + 4] = nb1;
        __syncthreads();

        if (k0 + 16 < K) {   // prefetch next tile (hidden behind compute)
            na0 = *(const float4*)(Aptr + (k0 + 16));
            na1 = *(const float4*)(Aptr + (k0 + 16) + 4);
            nb0 = *(const float4*)(Bptr + (size_t)(k0 + 16) * ldb);
            nb1 = *(const float4*)(Bptr + (size_t)(k0 + 16) * ldb + 4);
        }

        #pragma unroll
        for (int kk = 0; kk < 16; kk++) {
            float4 ax = *(const float4*)&As[kk][tm];
            float4 ay = *(const float4*)&As[kk][tm + 64];
            float4 bx = *(const float4*)&Bs[kk][tn];
            float4 by = *(const float4*)&Bs[kk][tn + 64];
            float av[8] = {ax.x, ax.y, ax.z, ax.w, ay.x, ay.y, ay.z, ay.w};
            float bv[8] = {bx.x, bx.y, bx.z, bx.w, by.x, by.y, by.z, by.w};
            #pragma unroll
            for (int i = 0; i < 8; i++)
                #pragma unroll
                for (int j = 0; j < 8; j++)
                    acc[i][j] += av[i] * bv[j];
        }
        __syncthreads();
    }

    #pragma unroll
    for (int i = 0; i < 8; i++) {
        int row = bm + tm + ((i < 4) ? i : (60 + i));
        const float* rrow = R ? (R + (size_t)row * ldc) : nullptr;
        float* crow = C + (size_t)row * ldc;
        #pragma unroll
        for (int jj = 0; jj < 2; jj++) {
            int col = bn + tn + jj * 64;
            float4 v;
            v.x = acc[i][jj*4 + 0] + bias[col + 0];
            v.y = acc[i][jj*4 + 1] + bias[col + 1];
            v.z = acc[i][jj*4 + 2] + bias[col + 2];
            v.w = acc[i][jj*4 + 3] + bias[col + 3];
            if (rrow) {
                v.x += rrow[col + 0]; v.y += rrow[col + 1];
                v.z += rrow[col + 2]; v.w += rrow[col + 3];
            }
            if (epi == 1) {
                v.x = gelu_f(v.x); v.y = gelu_f(v.y);
                v.z = gelu_f(v.z); v.w = gelu_f(v.w);
            }
            *(float4*)(crow + col) = v;
        }
    }
}

// ---------------------------------------------------------------- Attention
// One block per (chunk c, head h). 256 threads; lane-per-query (query = tid).
// Keys streamed in 32-key smem tiles from [c*CH-CH, c*CH+CH), RoPE fused on
// load for both q and k. Online softmax; per-warp tile skip on window bounds.
__global__ __launch_bounds__(256, 1)
void attn_kernel(const float* __restrict__ pos_sin,
                 const float* __restrict__ pos_cos,
                 const int* __restrict__ lenp)
{
    __shared__ float4 ks[32][16];
    __shared__ float4 vs[32][16];

    int c = blockIdx.x, h = blockIdx.y;
    int t = threadIdx.x;
    int w = t >> 5;
    int qtok = c * CH + t;
    unsigned lm   = ~((unsigned)(*lenp) - 1u);
    unsigned qseq = (unsigned)qtok & lm;

    const float SCALE = 0.125f;   // 1/sqrt(64)
    float q[64];
    {
        const float4* qp = (const float4*)(g_qkv + (size_t)qtok * QKVW + h * DH);
        const float4* sp = (const float4*)(pos_sin + (size_t)qtok * DH);
        const float4* cp = (const float4*)(pos_cos + (size_t)qtok * DH);
        #pragma unroll
        for (int i = 0; i < 16; i++) {
            float4 xv = qp[i], sv = sp[i], cv = cp[i];
            q[4*i + 0] = (xv.x * cv.x - xv.y * sv.x) * SCALE;
            q[4*i + 1] = (xv.y * cv.y + xv.x * sv.y) * SCALE;
            q[4*i + 2] = (xv.z * cv.z - xv.w * sv.z) * SCALE;
            q[4*i + 3] = (xv.w * cv.w + xv.z * sv.w) * SCALE;
        }
    }

    float o[64];
    #pragma unroll
    for (int d = 0; d < 64; d++) o[d] = 0.f;
    float m = -FLT_MAX, lsum = 0.f;

    int kt0 = (c == 0) ? 8 : 0;   // chunk 0: previous-chunk keys are all masked
    for (int kt = kt0; kt < 16; kt++) {
        int kbase = c * CH - CH + kt * 32;
        // cooperative tile load (k with fused RoPE, plus v)
        {
            int f0 = t * 2;
            #pragma unroll
            for (int i = 0; i < 2; i++) {
                int f = f0 + i;
                int row = f >> 4, col4 = f & 15;
                int ktok = kbase + row;
                const float4* kp = (const float4*)(g_qkv + (size_t)ktok * QKVW + HID     + h * DH) + col4;
                const float4* vp = (const float4*)(g_qkv + (size_t)ktok * QKVW + 2 * HID + h * DH) + col4;
                float4 kv = *kp, vv = *vp;
                float4 sv = ((const float4*)(pos_sin + (size_t)ktok * DH))[col4];
                float4 cv = ((const float4*)(pos_cos + (size_t)ktok * DH))[col4];
                float4 kr;
                kr.x = kv.x * cv.x - kv.y * sv.x;
                kr.y = kv.y * cv.y + kv.x * sv.y;
                kr.z = kv.z * cv.z - kv.w * sv.z;
                kr.w = kv.w * cv.w + kv.z * sv.w;
                ks[row][col4] = kr;
                vs[row][col4] = vv;
            }
        }
        __syncthreads();

        int qmin = c * CH + w * 32;
        bool active = (kbase <= qmin + 31) && (qmin - (kbase + 31) < WIN);
        if (active) {
            float s[32];
            float tmax = -FLT_MAX;
            unsigned anyvalid = 0;
            #pragma unroll
            for (int j = 0; j < 32; j++) {
                float dot = 0.f;
                #pragma unroll
                for (int dd = 0; dd < 16; dd++) {
                    float4 kk = ks[j][dd];
                    dot += q[4*dd + 0] * kk.x;
                    dot += q[4*dd + 1] * kk.y;
                    dot += q[4*dd + 2] * kk.z;
                    dot += q[4*dd + 3] * kk.w;
                }
                int ktok = kbase + j;
                int d = qtok - ktok;
                bool valid = (d >= 0) && (d < WIN) && (((unsigned)ktok & lm) == qseq);
                s[j] = valid ? dot : -FLT_MAX;
                if (valid) anyvalid = 1u;
                tmax = fmaxf(tmax, s[j]);
            }
            if (anyvalid) {
                float mnew = fmaxf(m, tmax);
                float corr = __expf(m - mnew);    // 0 on first active tile
                lsum *= corr;
                #pragma unroll
                for (int d = 0; d < 64; d++) o[d] *= corr;
                #pragma unroll
                for (int j = 0; j < 32; j++) {
                    float p = __expf(s[j] - mnew); // masked: exp(-inf) = 0
                    lsum += p;
                    #pragma unroll
                    for (int dd = 0; dd < 16; dd++) {
                        float4 vv = vs[j][dd];
                        o[4*dd + 0] += p * vv.x;
                        o[4*dd + 1] += p * vv.y;
                        o[4*dd + 2] += p * vv.z;
                        o[4*dd + 3] += p * vv.w;
                    }
                }
                m = mnew;
            }
        }
        __syncthreads();
    }

    float inv = 1.0f / lsum;   // safe: self-key always valid
    float4* op = (float4*)(g_comb + (size_t)qtok * COMBW + h * DH);
    #pragma unroll
    for (int dd = 0; dd < 16; dd++)
        op[dd] = make_float4(o[4*dd + 0] * inv, o[4*dd + 1] * inv,
                             o[4*dd + 2] * inv, o[4*dd + 3] * inv);
}

// ---------------------------------------------------------------- launch
extern "C" void kernel_launch(void* const* d_in, const int* in_sizes, int n_in,
                              void* d_out, int out_size)
{
    (void)in_sizes; (void)n_in; (void)out_size;
    const float* x        = (const float*)d_in[0];
    // d_in[1] = normed_ages (unused by reference)
    const float* pos_sin  = (const float*)d_in[2];
    const float* pos_cos  = (const float*)d_in[3];
    const float* ln_scale = (const float*)d_in[4];
    const float* ln_off   = (const float*)d_in[5];
    const float* w_in     = (const float*)d_in[6];
    const float* b_in     = (const float*)d_in[7];
    const float* w_out    = (const float*)d_in[8];
    const float* b_out    = (const float*)d_in[9];
    const int*   lenp     = (const int*)d_in[10];
    float* out = (float*)d_out;

    static float *p_xn = nullptr, *p_qkv = nullptr, *p_comb = nullptr;
    if (!p_xn) {
        cudaGetSymbolAddress((void**)&p_xn,   g_xn);
        cudaGetSymbolAddress((void**)&p_qkv,  g_qkv);
        cudaGetSymbolAddress((void**)&p_comb, g_comb);
    }

    ln_kernel<<<NTOK, 256>>>(x, ln_scale, ln_off);

    // qkv = xn @ w_in[:, :2304] + b_in[:2304]        [16384 x 2304]
    sgemm_kernel<<<dim3(QKVW / 128, NTOK / 128), 256>>>(
        p_xn, HID, w_in, MIDW, b_in, nullptr, p_qkv, QKVW,
        NTOK, QKVW, HID, 0);

    // comb[:, 768:] = gelu(xn @ w_in[:, 2304:] + b_in[2304:])   [16384 x 3072]
    sgemm_kernel<<<dim3(INTER / 128, NTOK / 128), 256>>>(
        p_xn, HID, w_in + QKVW, MIDW, b_in + QKVW, nullptr, p_comb + HID, COMBW,
        NTOK, INTER, HID, 1);

    // attn -> comb[:, :768] (RoPE fused)
    attn_kernel<<<dim3(NCHUNK, NH), 256>>>(pos_sin, pos_cos, lenp);

    // out = xn + comb @ w_out + b_out  [16384 x 768]
    sgemm_kernel<<<dim3(HID / 128, NTOK / 128), 256>>>(
        p_comb, COMBW, w_out, HID, b_out, p_xn, out, HID,
        NTOK, HID, COMBW, 0);
}

// round 6
// speedup vs baseline: 2.2460x; 2.2460x over previous
#include <cuda_runtime.h>
#include <cfloat>
#include <cstddef>
#include <cstdint>

#define HID   768
#define INTER 3072
#define NH    12
#define DH    64
#define NTOK  16384
#define WIN   256
#define CH    256
#define MIDW  (3*HID + INTER)   // 5376
#define QKVW  (3*HID)           // 2304
#define COMBW (HID + INTER)     // 3840
#define NCHUNK (NTOK / CH)      // 64

#define ASTR 36                       // smem row stride in floats (pad 4)
#define TILE_BYTES (128 * ASTR * 4)   // 18432 per operand tile
#define STAGE_BYTES (2 * TILE_BYTES)  // A + B
#define DSMEM_BYTES (2 * STAGE_BYTES) // 73728, double buffered

// Scratch (device globals: allocation inside kernel_launch is forbidden)
__device__ float g_xn  [(size_t)NTOK * HID];     //  50 MB
__device__ float g_qkv [(size_t)NTOK * QKVW];    // 151 MB
__device__ float g_comb[(size_t)NTOK * COMBW];   // 252 MB
__device__ float g_wt1 [(size_t)MIDW * HID];     //  16.5 MB  w_in^T  [5376][768]
__device__ float g_wt2 [(size_t)HID * COMBW];    //  11.8 MB  w_out^T [768][3840]

// ---------------------------------------------------------------- helpers
__device__ __forceinline__ uint32_t smem_u32(const void* p) {
    uint32_t a;
    asm("{ .reg .u64 t; cvta.to.shared.u64 t, %1; cvt.u32.u64 %0, t; }"
        : "=r"(a) : "l"(p));
    return a;
}
__device__ __forceinline__ float f2tf32_rna(float x) {
    uint32_t u;
    asm("cvt.rna.tf32.f32 %0, %1;" : "=r"(u) : "f"(x));
    return __uint_as_float(u);
}
__device__ __forceinline__ void cp_async16(uint32_t dst, const void* src) {
    asm volatile("cp.async.cg.shared.global [%0], [%1], 16;"
                 :: "r"(dst), "l"(src) : "memory");
}
__device__ __forceinline__ void cp_commit() {
    asm volatile("cp.async.commit_group;" ::: "memory");
}
__device__ __forceinline__ void cp_wait1() {
    asm volatile("cp.async.wait_group 1;" ::: "memory");
}
__device__ __forceinline__ void cp_wait0() {
    asm volatile("cp.async.wait_group 0;" ::: "memory");
}
__device__ __forceinline__ uint32_t lds32(uint32_t addr) {
    uint32_t v;
    asm volatile("ld.shared.b32 %0, [%1];" : "=r"(v) : "r"(addr));
    return v;
}
__device__ __forceinline__ void mma_tf32(float* d, const uint32_t* a, const uint32_t* b) {
    asm volatile(
        "mma.sync.aligned.m16n8k8.row.col.f32.tf32.tf32.f32 "
        "{%0,%1,%2,%3}, {%4,%5,%6,%7}, {%8,%9}, {%0,%1,%2,%3};"
        : "+f"(d[0]), "+f"(d[1]), "+f"(d[2]), "+f"(d[3])
        : "r"(a[0]), "r"(a[1]), "r"(a[2]), "r"(a[3]), "r"(b[0]), "r"(b[1]));
}

// ---------------------------------------------------------------- GELU (tanh approx = jax default)
__device__ __forceinline__ float gelu_f(float x) {
    float x3 = x * x * x;
    return 0.5f * x * (1.0f + tanhf(0.7978845608028654f * (x + 0.044715f * x3)));
}

// ---------------------------------------------------------------- LayerNorm
__global__ void ln_kernel(const float* __restrict__ x,
                          const float* __restrict__ gam,
                          const float* __restrict__ bet)
{
    int row = blockIdx.x;
    int t   = threadIdx.x;
    const float* xr = x + (size_t)row * HID;
    float v0 = xr[t], v1 = xr[t + 256], v2 = xr[t + 512];
    float s  = v0 + v1 + v2;
    float s2 = v0*v0 + v1*v1 + v2*v2;
    #pragma unroll
    for (int o = 16; o > 0; o >>= 1) {
        s  += __shfl_xor_sync(0xffffffffu, s,  o);
        s2 += __shfl_xor_sync(0xffffffffu, s2, o);
    }
    __shared__ float red0[8], red1[8];
    __shared__ float stat[2];
    int w = t >> 5, l = t & 31;
    if (l == 0) { red0[w] = s; red1[w] = s2; }
    __syncthreads();
    if (t == 0) {
        float ts = 0.f, ts2 = 0.f;
        #pragma unroll
        for (int i = 0; i < 8; i++) { ts += red0[i]; ts2 += red1[i]; }
        float mu  = ts * (1.0f / HID);
        float var = ts2 * (1.0f / HID) - mu * mu;
        stat[0] = mu;
        stat[1] = rsqrtf(var + 1e-5f);
    }
    __syncthreads();
    float mu = stat[0], inv = stat[1];
    float* o = g_xn + (size_t)row * HID;
    o[t]       = (v0 - mu) * inv * gam[t]       + bet[t];
    o[t + 256] = (v1 - mu) * inv * gam[t + 256] + bet[t + 256];
    o[t + 512] = (v2 - mu) * inv * gam[t + 512] + bet[t + 512];
}

// ---------------------------------------------------------------- Transpose (R x C -> C x R), dims % 32 == 0
// Also rounds weights to tf32 (rna) so the B operand is cleanly rounded.
__global__ void transpose_kernel(const float* __restrict__ in, float* __restrict__ out,
                                 int R, int C)
{
    __shared__ float tile[32][33];
    int bx = blockIdx.x * 32, by = blockIdx.y * 32;
    int tx = threadIdx.x, ty = threadIdx.y;
    #pragma unroll
    for (int i = 0; i < 32; i += 8)
        tile[ty + i][tx] = in[(size_t)(by + ty + i) * C + bx + tx];
    __syncthreads();
    #pragma unroll
    for (int i = 0; i < 32; i += 8)
        out[(size_t)(bx + ty + i) * R + by + tx] = f2tf32_rna(tile[tx][ty + i]);
}

// ---------------------------------------------------------------- HMMA tf32 GEMM
// C[128m x 128n] = epi( A[M,K](lda) @ Bt[n, K](ldb)^T + bias [+ R] )
// epi: 0 = none, 1 = gelu. K % 32 == 0. M % 128 == 0, N % 128 == 0.
__global__ __launch_bounds__(256)
void tgemm_kernel(const float* __restrict__ A, int lda,
                  const float* __restrict__ Bt, int ldb,
                  const float* __restrict__ bias,
                  const float* __restrict__ R,
                  float* __restrict__ C, int ldc,
                  int K, int epi)
{
    extern __shared__ float sm[];
    uint32_t sbase = smem_u32(sm);

    int t = threadIdx.x;
    int wid = t >> 5, lane = t & 31;
    int warp_m = (wid >> 2) * 64, warp_n = (wid & 3) * 32;
    int bm = blockIdx.y * 128, bn = blockIdx.x * 128;
    int r = lane >> 2, c = lane & 3;

    const float* Ag = A  + (size_t)bm * lda;
    const float* Bg = Bt + (size_t)bn * ldb;

    float acc[16][4];
    #pragma unroll
    for (int i = 0; i < 16; i++)
        #pragma unroll
        for (int j = 0; j < 4; j++) acc[i][j] = 0.f;

    // chunk mapping: ids t, t+256, t+512, t+768 ; id -> row id>>3, 16B piece id&7
    int cm[4], ck[4];
    #pragma unroll
    for (int i = 0; i < 4; i++) {
        int id = t + i * 256;
        cm[i] = id >> 3;
        ck[i] = (id & 7) * 4;     // float offset within 32-float row
    }

    auto load_stage = [&](int buf, int kbase) {
        uint32_t ab = sbase + (uint32_t)buf * STAGE_BYTES;
        uint32_t bb = ab + TILE_BYTES;
        #pragma unroll
        for (int i = 0; i < 4; i++) {
            cp_async16(ab + (uint32_t)(cm[i] * ASTR + ck[i]) * 4u,
                       Ag + (size_t)cm[i] * lda + kbase + ck[i]);
            cp_async16(bb + (uint32_t)(cm[i] * ASTR + ck[i]) * 4u,
                       Bg + (size_t)cm[i] * ldb + kbase + ck[i]);
        }
    };

    int S = K / 32;
    load_stage(0, 0);
    cp_commit();

    for (int s = 0; s < S; s++) {
        int buf = s & 1;
        if (s + 1 < S) {
            load_stage(buf ^ 1, (s + 1) * 32);
            cp_commit();
            cp_wait1();
        } else {
            cp_wait0();
        }
        __syncthreads();

        uint32_t ab = sbase + (uint32_t)buf * STAGE_BYTES;
        uint32_t bb = ab + TILE_BYTES;
        #pragma unroll
        for (int ks = 0; ks < 4; ks++) {
            int k0 = ks * 8;
            uint32_t af[4][4];
            #pragma unroll
            for (int mt = 0; mt < 4; mt++) {
                uint32_t base = ab + (uint32_t)((warp_m + mt * 16 + r) * ASTR + k0 + c) * 4u;
                af[mt][0] = lds32(base);
                af[mt][1] = lds32(base + 8u * ASTR * 4u);
                af[mt][2] = lds32(base + 16u);
                af[mt][3] = lds32(base + 8u * ASTR * 4u + 16u);
            }
            uint32_t bf[4][2];
            #pragma unroll
            for (int nt = 0; nt < 4; nt++) {
                uint32_t base = bb + (uint32_t)((warp_n + nt * 8 + r) * ASTR + k0 + c) * 4u;
                bf[nt][0] = lds32(base);
                bf[nt][1] = lds32(base + 16u);
            }
            #pragma unroll
            for (int mt = 0; mt < 4; mt++)
                #pragma unroll
                for (int nt = 0; nt < 4; nt++)
                    mma_tf32(acc[mt * 4 + nt], af[mt], bf[nt]);
        }
        __syncthreads();
    }

    // epilogue: c0:(r,2c) c1:(r,2c+1) c2:(r+8,2c) c3:(r+8,2c+1)
    #pragma unroll
    for (int mt = 0; mt < 4; mt++) {
        #pragma unroll
        for (int nt = 0; nt < 4; nt++) {
            float* a4 = acc[mt * 4 + nt];
            int gm0 = bm + warp_m + mt * 16 + r;
            int gn  = bn + warp_n + nt * 8 + c * 2;
            float bx = bias[gn], by = bias[gn + 1];
            #pragma unroll
            for (int half = 0; half < 2; half++) {
                int gm = gm0 + half * 8;
                float vx = a4[half * 2 + 0] + bx;
                float vy = a4[half * 2 + 1] + by;
                if (R) {
                    const float* rp = R + (size_t)gm * ldc + gn;
                    vx += rp[0]; vy += rp[1];
                }
                if (epi == 1) { vx = gelu_f(vx); vy = gelu_f(vy); }
                *(float2*)(C + (size_t)gm * ldc + gn) = make_float2(vx, vy);
            }
        }
    }
}

// ---------------------------------------------------------------- Attention (unchanged from R3)
__global__ __launch_bounds__(256, 1)
void attn_kernel(const float* __restrict__ pos_sin,
                 const float* __restrict__ pos_cos,
                 const int* __restrict__ lenp)
{
    __shared__ float4 ks[32][16];
    __shared__ float4 vs[32][16];

    int c = blockIdx.x, h = blockIdx.y;
    int t = threadIdx.x;
    int w = t >> 5;
    int qtok = c * CH + t;
    unsigned lm   = ~((unsigned)(*lenp) - 1u);
    unsigned qseq = (unsigned)qtok & lm;

    const float SCALE = 0.125f;
    float q[64];
    {
        const float4* qp = (const float4*)(g_qkv + (size_t)qtok * QKVW + h * DH);
        const float4* sp = (const float4*)(pos_sin + (size_t)qtok * DH);
        const float4* cp = (const float4*)(pos_cos + (size_t)qtok * DH);
        #pragma unroll
        for (int i = 0; i < 16; i++) {
            float4 xv = qp[i], sv = sp[i], cv = cp[i];
            q[4*i + 0] = (xv.x * cv.x - xv.y * sv.x) * SCALE;
            q[4*i + 1] = (xv.y * cv.y + xv.x * sv.y) * SCALE;
            q[4*i + 2] = (xv.z * cv.z - xv.w * sv.z) * SCALE;
            q[4*i + 3] = (xv.w * cv.w + xv.z * sv.w) * SCALE;
        }
    }

    float o[64];
    #pragma unroll
    for (int d = 0; d < 64; d++) o[d] = 0.f;
    float m = -FLT_MAX, lsum = 0.f;

    int kt0 = (c == 0) ? 8 : 0;
    for (int kt = kt0; kt < 16; kt++) {
        int kbase = c * CH - CH + kt * 32;
        {
            int f0 = t * 2;
            #pragma unroll
            for (int i = 0; i < 2; i++) {
                int f = f0 + i;
                int row = f >> 4, col4 = f & 15;
                int ktok = kbase + row;
                const float4* kp = (const float4*)(g_qkv + (size_t)ktok * QKVW + HID     + h * DH) + col4;
                const float4* vp = (const float4*)(g_qkv + (size_t)ktok * QKVW + 2 * HID + h * DH) + col4;
                float4 kv = *kp, vv = *vp;
                float4 sv = ((const float4*)(pos_sin + (size_t)ktok * DH))[col4];
                float4 cv = ((const float4*)(pos_cos + (size_t)ktok * DH))[col4];
                float4 kr;
                kr.x = kv.x * cv.x - kv.y * sv.x;
                kr.y = kv.y * cv.y + kv.x * sv.y;
                kr.z = kv.z * cv.z - kv.w * sv.z;
                kr.w = kv.w * cv.w + kv.z * sv.w;
                ks[row][col4] = kr;
                vs[row][col4] = vv;
            }
        }
        __syncthreads();

        int qmin = c * CH + w * 32;
        bool active = (kbase <= qmin + 31) && (qmin - (kbase + 31) < WIN);
        if (active) {
            float s[32];
            float tmax = -FLT_MAX;
            unsigned anyvalid = 0;
            #pragma unroll
            for (int j = 0; j < 32; j++) {
                float dot = 0.f;
                #pragma unroll
                for (int dd = 0; dd < 16; dd++) {
                    float4 kk = ks[j][dd];
                    dot += q[4*dd + 0] * kk.x;
                    dot += q[4*dd + 1] * kk.y;
                    dot += q[4*dd + 2] * kk.z;
                    dot += q[4*dd + 3] * kk.w;
                }
                int ktok = kbase + j;
                int d = qtok - ktok;
                bool valid = (d >= 0) && (d < WIN) && (((unsigned)ktok & lm) == qseq);
                s[j] = valid ? dot : -FLT_MAX;
                if (valid) anyvalid = 1u;
                tmax = fmaxf(tmax, s[j]);
            }
            if (anyvalid) {
                float mnew = fmaxf(m, tmax);
                float corr = __expf(m - mnew);
                lsum *= corr;
                #pragma unroll
                for (int d = 0; d < 64; d++) o[d] *= corr;
                #pragma unroll
                for (int j = 0; j < 32; j++) {
                    float p = __expf(s[j] - mnew);
                    lsum += p;
                    #pragma unroll
                    for (int dd = 0; dd < 16; dd++) {
                        float4 vv = vs[j][dd];
                        o[4*dd + 0] += p * vv.x;
                        o[4*dd + 1] += p * vv.y;
                        o[4*dd + 2] += p * vv.z;
                        o[4*dd + 3] += p * vv.w;
                    }
                }
                m = mnew;
            }
        }
        __syncthreads();
    }

    float inv = 1.0f / lsum;
    float4* op = (float4*)(g_comb + (size_t)qtok * COMBW + h * DH);
    #pragma unroll
    for (int dd = 0; dd < 16; dd++)
        op[dd] = make_float4(o[4*dd + 0] * inv, o[4*dd + 1] * inv,
                             o[4*dd + 2] * inv, o[4*dd + 3] * inv);
}

// ---------------------------------------------------------------- launch
extern "C" void kernel_launch(void* const* d_in, const int* in_sizes, int n_in,
                              void* d_out, int out_size)
{
    (void)in_sizes; (void)n_in; (void)out_size;
    const float* x        = (const float*)d_in[0];
    const float* pos_sin  = (const float*)d_in[2];
    const float* pos_cos  = (const float*)d_in[3];
    const float* ln_scale = (const float*)d_in[4];
    const float* ln_off   = (const float*)d_in[5];
    const float* w_in     = (const float*)d_in[6];
    const float* b_in     = (const float*)d_in[7];
    const float* w_out    = (const float*)d_in[8];
    const float* b_out    = (const float*)d_in[9];
    const int*   lenp     = (const int*)d_in[10];
    float* out = (float*)d_out;

    static float *p_xn = nullptr, *p_qkv = nullptr, *p_comb = nullptr,
                 *p_wt1 = nullptr, *p_wt2 = nullptr;
    if (!p_xn) {
        cudaGetSymbolAddress((void**)&p_xn,   g_xn);
        cudaGetSymbolAddress((void**)&p_qkv,  g_qkv);
        cudaGetSymbolAddress((void**)&p_comb, g_comb);
        cudaGetSymbolAddress((void**)&p_wt1,  g_wt1);
        cudaGetSymbolAddress((void**)&p_wt2,  g_wt2);
        cudaFuncSetAttribute(tgemm_kernel,
                             cudaFuncAttributeMaxDynamicSharedMemorySize, DSMEM_BYTES);
    }

    ln_kernel<<<NTOK, 256>>>(x, ln_scale, ln_off);

    // transpose + tf32-round weights
    transpose_kernel<<<dim3(MIDW / 32, HID / 32),   dim3(32, 8)>>>(w_in,  p_wt1, HID,   MIDW);
    transpose_kernel<<<dim3(HID / 32,  COMBW / 32), dim3(32, 8)>>>(w_out, p_wt2, COMBW, HID);

    // qkv = xn @ w_in[:, :2304] + b_in[:2304]
    tgemm_kernel<<<dim3(QKVW / 128, NTOK / 128), 256, DSMEM_BYTES>>>(
        p_xn, HID, p_wt1, HID, b_in, nullptr, p_qkv, QKVW, HID, 0);

    // comb[:, 768:] = gelu(xn @ w_in[:, 2304:] + b_in[2304:])
    tgemm_kernel<<<dim3(INTER / 128, NTOK / 128), 256, DSMEM_BYTES>>>(
        p_xn, HID, p_wt1 + (size_t)QKVW * HID, HID, b_in + QKVW, nullptr,
        p_comb + HID, COMBW, HID, 1);

    // attn -> comb[:, :768] (RoPE fused)
    attn_kernel<<<dim3(NCHUNK, NH), 256>>>(pos_sin, pos_cos, lenp);

    // out = xn + comb @ w_out + b_out
    tgemm_kernel<<<dim3(HID / 128, NTOK / 128), 256, DSMEM_BYTES>>>(
        p_comb, COMBW, p_wt2, COMBW, b_out, p_xn, out, HID, COMBW, 0);
}

// round 7
// speedup vs baseline: 2.3328x; 1.0387x over previous
#include <cuda_runtime.h>
#include <cfloat>
#include <cstddef>
#include <cstdint>

#define HID   768
#define INTER 3072
#define NH    12
#define DH    64
#define NTOK  16384
#define WIN   256
#define CH    256
#define MIDW  (3*HID + INTER)   // 5376
#define QKVW  (3*HID)           // 2304
#define COMBW (HID + INTER)     // 3840
#define NCHUNK (NTOK / CH)      // 64

#define ASTR 36                       // smem row stride in floats (pad 4)
#define TILE_BYTES (128 * ASTR * 4)   // 18432 per operand tile
#define STAGE_BYTES (2 * TILE_BYTES)  // A + B
#define DSMEM_BYTES (2 * STAGE_BYTES) // 73728, double buffered

// Scratch (device globals: allocation inside kernel_launch is forbidden)
__device__ float g_xn  [(size_t)NTOK * HID];     //  50 MB
__device__ float g_qkv [(size_t)NTOK * QKVW];    // 151 MB
__device__ float g_comb[(size_t)NTOK * COMBW];   // 252 MB
__device__ float g_wt1 [(size_t)MIDW * HID];     //  16.5 MB  w_in^T  [5376][768]
__device__ float g_wt2 [(size_t)HID * COMBW];    //  11.8 MB  w_out^T [768][3840]

// ---------------------------------------------------------------- helpers
__device__ __forceinline__ uint32_t smem_u32(const void* p) {
    uint32_t a;
    asm("{ .reg .u64 t; cvta.to.shared.u64 t, %1; cvt.u32.u64 %0, t; }"
        : "=r"(a) : "l"(p));
    return a;
}
__device__ __forceinline__ float f2tf32_rna(float x) {
    uint32_t u;
    asm("cvt.rna.tf32.f32 %0, %1;" : "=r"(u) : "f"(x));
    return __uint_as_float(u);
}
__device__ __forceinline__ void cp_async16(uint32_t dst, const void* src) {
    asm volatile("cp.async.cg.shared.global [%0], [%1], 16;"
                 :: "r"(dst), "l"(src) : "memory");
}
__device__ __forceinline__ void cp_commit() {
    asm volatile("cp.async.commit_group;" ::: "memory");
}
__device__ __forceinline__ void cp_wait1() {
    asm volatile("cp.async.wait_group 1;" ::: "memory");
}
__device__ __forceinline__ void cp_wait0() {
    asm volatile("cp.async.wait_group 0;" ::: "memory");
}
__device__ __forceinline__ uint32_t lds32(uint32_t addr) {
    uint32_t v;
    asm volatile("ld.shared.b32 %0, [%1];" : "=r"(v) : "r"(addr));
    return v;
}
__device__ __forceinline__ void mma_tf32(float* d, const uint32_t* a, const uint32_t* b) {
    asm volatile(
        "mma.sync.aligned.m16n8k8.row.col.f32.tf32.tf32.f32 "
        "{%0,%1,%2,%3}, {%4,%5,%6,%7}, {%8,%9}, {%0,%1,%2,%3};"
        : "+f"(d[0]), "+f"(d[1]), "+f"(d[2]), "+f"(d[3])
        : "r"(a[0]), "r"(a[1]), "r"(a[2]), "r"(a[3]), "r"(b[0]), "r"(b[1]));
}

// ---------------------------------------------------------------- GELU (tanh approx = jax default)
__device__ __forceinline__ float gelu_f(float x) {
    float x3 = x * x * x;
    return 0.5f * x * (1.0f + tanhf(0.7978845608028654f * (x + 0.044715f * x3)));
}

// ---------------------------------------------------------------- LayerNorm
__global__ void ln_kernel(const float* __restrict__ x,
                          const float* __restrict__ gam,
                          const float* __restrict__ bet)
{
    int row = blockIdx.x;
    int t   = threadIdx.x;
    const float* xr = x + (size_t)row * HID;
    float v0 = xr[t], v1 = xr[t + 256], v2 = xr[t + 512];
    float s  = v0 + v1 + v2;
    float s2 = v0*v0 + v1*v1 + v2*v2;
    #pragma unroll
    for (int o = 16; o > 0; o >>= 1) {
        s  += __shfl_xor_sync(0xffffffffu, s,  o);
        s2 += __shfl_xor_sync(0xffffffffu, s2, o);
    }
    __shared__ float red0[8], red1[8];
    __shared__ float stat[2];
    int w = t >> 5, l = t & 31;
    if (l == 0) { red0[w] = s; red1[w] = s2; }
    __syncthreads();
    if (t == 0) {
        float ts = 0.f, ts2 = 0.f;
        #pragma unroll
        for (int i = 0; i < 8; i++) { ts += red0[i]; ts2 += red1[i]; }
        float mu  = ts * (1.0f / HID);
        float var = ts2 * (1.0f / HID) - mu * mu;
        stat[0] = mu;
        stat[1] = rsqrtf(var + 1e-5f);
    }
    __syncthreads();
    float mu = stat[0], inv = stat[1];
    float* o = g_xn + (size_t)row * HID;
    o[t]       = (v0 - mu) * inv * gam[t]       + bet[t];
    o[t + 256] = (v1 - mu) * inv * gam[t + 256] + bet[t + 256];
    o[t + 512] = (v2 - mu) * inv * gam[t + 512] + bet[t + 512];
}

// ---------------------------------------------------------------- Transpose (R x C -> C x R), dims % 32 == 0
// Also rounds weights to tf32 (rna) so the B operand is cleanly rounded.
__global__ void transpose_kernel(const float* __restrict__ in, float* __restrict__ out,
                                 int R, int C)
{
    __shared__ float tile[32][33];
    int bx = blockIdx.x * 32, by = blockIdx.y * 32;
    int tx = threadIdx.x, ty = threadIdx.y;
    #pragma unroll
    for (int i = 0; i < 32; i += 8)
        tile[ty + i][tx] = in[(size_t)(by + ty + i) * C + bx + tx];
    __syncthreads();
    #pragma unroll
    for (int i = 0; i < 32; i += 8)
        out[(size_t)(bx + ty + i) * R + by + tx] = f2tf32_rna(tile[tx][ty + i]);
}

// ---------------------------------------------------------------- HMMA tf32 GEMM (unchanged from R6)
__global__ __launch_bounds__(256)
void tgemm_kernel(const float* __restrict__ A, int lda,
                  const float* __restrict__ Bt, int ldb,
                  const float* __restrict__ bias,
                  const float* __restrict__ R,
                  float* __restrict__ C, int ldc,
                  int K, int epi)
{
    extern __shared__ float sm[];
    uint32_t sbase = smem_u32(sm);

    int t = threadIdx.x;
    int wid = t >> 5, lane = t & 31;
    int warp_m = (wid >> 2) * 64, warp_n = (wid & 3) * 32;
    int bm = blockIdx.y * 128, bn = blockIdx.x * 128;
    int r = lane >> 2, c = lane & 3;

    const float* Ag = A  + (size_t)bm * lda;
    const float* Bg = Bt + (size_t)bn * ldb;

    float acc[16][4];
    #pragma unroll
    for (int i = 0; i < 16; i++)
        #pragma unroll
        for (int j = 0; j < 4; j++) acc[i][j] = 0.f;

    int cm[4], ck[4];
    #pragma unroll
    for (int i = 0; i < 4; i++) {
        int id = t + i * 256;
        cm[i] = id >> 3;
        ck[i] = (id & 7) * 4;
    }

    auto load_stage = [&](int buf, int kbase) {
        uint32_t ab = sbase + (uint32_t)buf * STAGE_BYTES;
        uint32_t bb = ab + TILE_BYTES;
        #pragma unroll
        for (int i = 0; i < 4; i++) {
            cp_async16(ab + (uint32_t)(cm[i] * ASTR + ck[i]) * 4u,
                       Ag + (size_t)cm[i] * lda + kbase + ck[i]);
            cp_async16(bb + (uint32_t)(cm[i] * ASTR + ck[i]) * 4u,
                       Bg + (size_t)cm[i] * ldb + kbase + ck[i]);
        }
    };

    int S = K / 32;
    load_stage(0, 0);
    cp_commit();

    for (int s = 0; s < S; s++) {
        int buf = s & 1;
        if (s + 1 < S) {
            load_stage(buf ^ 1, (s + 1) * 32);
            cp_commit();
            cp_wait1();
        } else {
            cp_wait0();
        }
        __syncthreads();

        uint32_t ab = sbase + (uint32_t)buf * STAGE_BYTES;
        uint32_t bb = ab + TILE_BYTES;
        #pragma unroll
        for (int ks = 0; ks < 4; ks++) {
            int k0 = ks * 8;
            uint32_t af[4][4];
            #pragma unroll
            for (int mt = 0; mt < 4; mt++) {
                uint32_t base = ab + (uint32_t)((warp_m + mt * 16 + r) * ASTR + k0 + c) * 4u;
                af[mt][0] = lds32(base);
                af[mt][1] = lds32(base + 8u * ASTR * 4u);
                af[mt][2] = lds32(base + 16u);
                af[mt][3] = lds32(base + 8u * ASTR * 4u + 16u);
            }
            uint32_t bf[4][2];
            #pragma unroll
            for (int nt = 0; nt < 4; nt++) {
                uint32_t base = bb + (uint32_t)((warp_n + nt * 8 + r) * ASTR + k0 + c) * 4u;
                bf[nt][0] = lds32(base);
                bf[nt][1] = lds32(base + 16u);
            }
            #pragma unroll
            for (int mt = 0; mt < 4; mt++)
                #pragma unroll
                for (int nt = 0; nt < 4; nt++)
                    mma_tf32(acc[mt * 4 + nt], af[mt], bf[nt]);
        }
        __syncthreads();
    }

    #pragma unroll
    for (int mt = 0; mt < 4; mt++) {
        #pragma unroll
        for (int nt = 0; nt < 4; nt++) {
            float* a4 = acc[mt * 4 + nt];
            int gm0 = bm + warp_m + mt * 16 + r;
            int gn  = bn + warp_n + nt * 8 + c * 2;
            float bx = bias[gn], by = bias[gn + 1];
            #pragma unroll
            for (int half = 0; half < 2; half++) {
                int gm = gm0 + half * 8;
                float vx = a4[half * 2 + 0] + bx;
                float vy = a4[half * 2 + 1] + by;
                if (R) {
                    const float* rp = R + (size_t)gm * ldc + gn;
                    vx += rp[0]; vy += rp[1];
                }
                if (epi == 1) { vx = gelu_f(vx); vy = gelu_f(vy); }
                *(float2*)(C + (size_t)gm * ldc + gn) = make_float2(vx, vy);
            }
        }
    }
}

// ---------------------------------------------------------------- Attention
// Lane-pair split: each query handled by 2 adjacent lanes, each owning 32 of
// the 64 dims. Block = 128 queries (half a chunk), 256 threads. Softmax state
// is replicated in the pair (bit-identical via commutative pair reduction).
__global__ __launch_bounds__(256, 2)
void attn_kernel(const float* __restrict__ pos_sin,
                 const float* __restrict__ pos_cos,
                 const int* __restrict__ lenp)
{
    __shared__ float4 ks[32][16];
    __shared__ float4 vs[32][16];

    int bx = blockIdx.x;
    int c  = bx >> 1, qh = bx & 1;
    int h  = blockIdx.y;
    int t  = threadIdx.x;
    int w  = t >> 5;                 // warp: 16 consecutive queries
    int ql = t >> 1;                 // local query 0..127
    int seg = t & 1;                 // dim half: [seg*32, seg*32+32)
    int qtok = c * CH + qh * 128 + ql;
    unsigned lm   = ~((unsigned)(*lenp) - 1u);
    unsigned qseq = (unsigned)qtok & lm;

    const float SCALE = 0.125f;      // 1/sqrt(64)
    float q[32];
    {
        const float4* qp = (const float4*)(g_qkv + (size_t)qtok * QKVW + h * DH + seg * 32);
        const float4* sp = (const float4*)(pos_sin + (size_t)qtok * DH + seg * 32);
        const float4* cp = (const float4*)(pos_cos + (size_t)qtok * DH + seg * 32);
        #pragma unroll
        for (int i = 0; i < 8; i++) {
            float4 xv = qp[i], sv = sp[i], cv = cp[i];
            q[4*i + 0] = (xv.x * cv.x - xv.y * sv.x) * SCALE;
            q[4*i + 1] = (xv.y * cv.y + xv.x * sv.y) * SCALE;
            q[4*i + 2] = (xv.z * cv.z - xv.w * sv.z) * SCALE;
            q[4*i + 3] = (xv.w * cv.w + xv.z * sv.w) * SCALE;
        }
    }

    float o[32];
    #pragma unroll
    for (int d = 0; d < 32; d++) o[d] = 0.f;
    float m = -FLT_MAX, lsum = 0.f;

    // tiles covering keys [c*CH-256 + kt*32, +32); this block half needs 12 tiles
    int kt_beg = qh * 4, kt_end = qh * 4 + 12;
    if (c == 0 && kt_beg < 8) kt_beg = 8;   // chunk 0: no previous chunk

    for (int kt = kt_beg; kt < kt_end; kt++) {
        int kbase = c * CH - CH + kt * 32;
        // cooperative tile load: 512 float4 per array, 2 per thread
        #pragma unroll
        for (int i = 0; i < 2; i++) {
            int f = t * 2 + i;
            int row = f >> 4, col4 = f & 15;
            int ktok = kbase + row;
            const float4* kp = (const float4*)(g_qkv + (size_t)ktok * QKVW + HID     + h * DH) + col4;
            const float4* vp = (const float4*)(g_qkv + (size_t)ktok * QKVW + 2 * HID + h * DH) + col4;
            float4 kv = *kp, vv = *vp;
            float4 svv = ((const float4*)(pos_sin + (size_t)ktok * DH))[col4];
            float4 cvv = ((const float4*)(pos_cos + (size_t)ktok * DH))[col4];
            float4 kr;
            kr.x = kv.x * cvv.x - kv.y * svv.x;
            kr.y = kv.y * cvv.y + kv.x * svv.y;
            kr.z = kv.z * cvv.z - kv.w * svv.z;
            kr.w = kv.w * cvv.w + kv.z * svv.w;
            ks[row][col4] = kr;
            vs[row][col4] = vv;
        }
        __syncthreads();

        int qmin = c * CH + qh * 128 + w * 16;
        bool active = (kbase <= qmin + 15) && (qmin - (kbase + 31) < WIN);
        if (active) {
            #pragma unroll
            for (int half = 0; half < 2; half++) {
                float s[16];
                float tmax = -FLT_MAX;
                bool any = false;
                #pragma unroll
                for (int j = 0; j < 16; j++) {
                    int row = half * 16 + j;
                    float dot = 0.f;
                    #pragma unroll
                    for (int dd = 0; dd < 8; dd++) {
                        float4 kk = ks[row][seg * 8 + dd];
                        dot += q[4*dd + 0] * kk.x + q[4*dd + 1] * kk.y
                             + q[4*dd + 2] * kk.z + q[4*dd + 3] * kk.w;
                    }
                    dot += __shfl_xor_sync(0xffffffffu, dot, 1);   // pair-reduce
                    int ktok = kbase + row;
                    int d = qtok - ktok;
                    bool valid = (d >= 0) && (d < WIN) && (((unsigned)ktok & lm) == qseq);
                    s[j] = valid ? dot : -FLT_MAX;
                    any |= valid;
                    tmax = fmaxf(tmax, s[j]);
                }
                if (any) {
                    float mnew = fmaxf(m, tmax);
                    float corr = __expf(m - mnew);
                    lsum *= corr;
                    #pragma unroll
                    for (int d = 0; d < 32; d++) o[d] *= corr;
                    #pragma unroll
                    for (int j = 0; j < 16; j++) {
                        float p = __expf(s[j] - mnew);
                        lsum += p;
                        int row = half * 16 + j;
                        #pragma unroll
                        for (int dd = 0; dd < 8; dd++) {
                            float4 vv = vs[row][seg * 8 + dd];
                            o[4*dd + 0] += p * vv.x; o[4*dd + 1] += p * vv.y;
                            o[4*dd + 2] += p * vv.z; o[4*dd + 3] += p * vv.w;
                        }
                    }
                    m = mnew;
                }
            }
        }
        __syncthreads();
    }

    float inv = 1.0f / lsum;   // self-key always valid
    float4* op = (float4*)(g_comb + (size_t)qtok * COMBW + h * DH + seg * 32);
    #pragma unroll
    for (int dd = 0; dd < 8; dd++)
        op[dd] = make_float4(o[4*dd + 0] * inv, o[4*dd + 1] * inv,
                             o[4*dd + 2] * inv, o[4*dd + 3] * inv);
}

// ---------------------------------------------------------------- launch
extern "C" void kernel_launch(void* const* d_in, const int* in_sizes, int n_in,
                              void* d_out, int out_size)
{
    (void)in_sizes; (void)n_in; (void)out_size;
    const float* x        = (const float*)d_in[0];
    const float* pos_sin  = (const float*)d_in[2];
    const float* pos_cos  = (const float*)d_in[3];
    const float* ln_scale = (const float*)d_in[4];
    const float* ln_off   = (const float*)d_in[5];
    const float* w_in     = (const float*)d_in[6];
    const float* b_in     = (const float*)d_in[7];
    const float* w_out    = (const float*)d_in[8];
    const float* b_out    = (const float*)d_in[9];
    const int*   lenp     = (const int*)d_in[10];
    float* out = (float*)d_out;

    static float *p_xn = nullptr, *p_qkv = nullptr, *p_comb = nullptr,
                 *p_wt1 = nullptr, *p_wt2 = nullptr;
    static cudaStream_t s1 = nullptr;
    static cudaEvent_t e0 = nullptr, eT = nullptr, eLN = nullptr, eF = nullptr;
    if (!p_xn) {
        cudaGetSymbolAddress((void**)&p_xn,   g_xn);
        cudaGetSymbolAddress((void**)&p_qkv,  g_qkv);
        cudaGetSymbolAddress((void**)&p_comb, g_comb);
        cudaGetSymbolAddress((void**)&p_wt1,  g_wt1);
        cudaGetSymbolAddress((void**)&p_wt2,  g_wt2);
        cudaFuncSetAttribute(tgemm_kernel,
                             cudaFuncAttributeMaxDynamicSharedMemorySize, DSMEM_BYTES);
        cudaStreamCreateWithFlags(&s1, cudaStreamNonBlocking);
        cudaEventCreateWithFlags(&e0,  cudaEventDisableTiming);
        cudaEventCreateWithFlags(&eT,  cudaEventDisableTiming);
        cudaEventCreateWithFlags(&eLN, cudaEventDisableTiming);
        cudaEventCreateWithFlags(&eF,  cudaEventDisableTiming);
    }

    // fork s1 from the (captured) default stream
    cudaEventRecord(e0, 0);
    cudaStreamWaitEvent(s1, e0, 0);

    // s1: weight transposes (+tf32 round); s0: layernorm
    transpose_kernel<<<dim3(MIDW / 32, HID / 32),   dim3(32, 8), 0, s1>>>(w_in,  p_wt1, HID,   MIDW);
    transpose_kernel<<<dim3(HID / 32,  COMBW / 32), dim3(32, 8), 0, s1>>>(w_out, p_wt2, COMBW, HID);
    ln_kernel<<<NTOK, 256>>>(x, ln_scale, ln_off);
    cudaEventRecord(eLN, 0);

    // s0: QKV GEMM (needs wt1 from s1)
    cudaEventRecord(eT, s1);
    cudaStreamWaitEvent(0, eT, 0);
    tgemm_kernel<<<dim3(QKVW / 128, NTOK / 128), 256, DSMEM_BYTES>>>(
        p_xn, HID, p_wt1, HID, b_in, nullptr, p_qkv, QKVW, HID, 0);

    // s1: FF GEMM + gelu (needs ln; wt1 already on s1) — overlaps QKV + attn
    cudaStreamWaitEvent(s1, eLN, 0);
    tgemm_kernel<<<dim3(INTER / 128, NTOK / 128), 256, DSMEM_BYTES, s1>>>(
        p_xn, HID, p_wt1 + (size_t)QKVW * HID, HID, b_in + QKVW, nullptr,
        p_comb + HID, COMBW, HID, 1);
    cudaEventRecord(eF, s1);

    // s0: attention (needs qkv) -> comb[:, :768]
    attn_kernel<<<dim3(NCHUNK * 2, NH), 256>>>(pos_sin, pos_cos, lenp);

    // join, then s0: out = xn + comb @ w_out + b_out
    cudaStreamWaitEvent(0, eF, 0);
    tgemm_kernel<<<dim3(HID / 128, NTOK / 128), 256, DSMEM_BYTES>>>(
        p_comb, COMBW, p_wt2, COMBW, b_out, p_xn, out, HID, COMBW, 0);
}

// round 8
// speedup vs baseline: 2.3728x; 1.0172x over previous
#include <cuda_runtime.h>
#include <cfloat>
#include <cstddef>
#include <cstdint>

#define HID   768
#define INTER 3072
#define NH    12
#define DH    64
#define NTOK  16384
#define WIN   256
#define CH    256
#define MIDW  (3*HID + INTER)   // 5376
#define QKVW  (3*HID)           // 2304
#define COMBW (HID + INTER)     // 3840
#define NCHUNK (NTOK / CH)      // 64

#define ASTR 36                       // smem row stride in floats (pad 4)
#define TILE_BYTES (128 * ASTR * 4)   // 18432 per operand tile
#define STAGE_BYTES (2 * TILE_BYTES)  // A + B
#define DSMEM_BYTES (2 * STAGE_BYTES) // 73728, double buffered

// Scratch (device globals: allocation inside kernel_launch is forbidden)
__device__ float g_xn  [(size_t)NTOK * HID];     //  50 MB
__device__ float g_qkv [(size_t)NTOK * QKVW];    // 151 MB
__device__ float g_comb[(size_t)NTOK * COMBW];   // 252 MB
__device__ float g_wt1 [(size_t)MIDW * HID];     //  16.5 MB  w_in^T  [5376][768]
__device__ float g_wt2 [(size_t)HID * COMBW];    //  11.8 MB  w_out^T [768][3840]

// ---------------------------------------------------------------- helpers
__device__ __forceinline__ uint32_t smem_u32(const void* p) {
    uint32_t a;
    asm("{ .reg .u64 t; cvta.to.shared.u64 t, %1; cvt.u32.u64 %0, t; }"
        : "=r"(a) : "l"(p));
    return a;
}
__device__ __forceinline__ float f2tf32_rna(float x) {
    uint32_t u;
    asm("cvt.rna.tf32.f32 %0, %1;" : "=r"(u) : "f"(x));
    return __uint_as_float(u);
}
__device__ __forceinline__ void cp_async16(uint32_t dst, const void* src) {
    asm volatile("cp.async.cg.shared.global [%0], [%1], 16;"
                 :: "r"(dst), "l"(src) : "memory");
}
__device__ __forceinline__ void cp_commit() {
    asm volatile("cp.async.commit_group;" ::: "memory");
}
__device__ __forceinline__ void cp_wait1() {
    asm volatile("cp.async.wait_group 1;" ::: "memory");
}
__device__ __forceinline__ void cp_wait0() {
    asm volatile("cp.async.wait_group 0;" ::: "memory");
}
__device__ __forceinline__ uint32_t lds32(uint32_t addr) {
    uint32_t v;
    asm volatile("ld.shared.b32 %0, [%1];" : "=r"(v) : "r"(addr));
    return v;
}
__device__ __forceinline__ void mma_tf32(float* d, const uint32_t* a, const uint32_t* b) {
    asm volatile(
        "mma.sync.aligned.m16n8k8.row.col.f32.tf32.tf32.f32 "
        "{%0,%1,%2,%3}, {%4,%5,%6,%7}, {%8,%9}, {%0,%1,%2,%3};"
        : "+f"(d[0]), "+f"(d[1]), "+f"(d[2]), "+f"(d[3])
        : "r"(a[0]), "r"(a[1]), "r"(a[2]), "r"(a[3]), "r"(b[0]), "r"(b[1]));
}

// ---------------------------------------------------------------- GELU (tanh approx = jax default)
__device__ __forceinline__ float gelu_f(float x) {
    float x3 = x * x * x;
    return 0.5f * x * (1.0f + tanhf(0.7978845608028654f * (x + 0.044715f * x3)));
}

// ---------------------------------------------------------------- LayerNorm
__global__ void ln_kernel(const float* __restrict__ x,
                          const float* __restrict__ gam,
                          const float* __restrict__ bet)
{
    int row = blockIdx.x;
    int t   = threadIdx.x;
    const float* xr = x + (size_t)row * HID;
    float v0 = xr[t], v1 = xr[t + 256], v2 = xr[t + 512];
    float s  = v0 + v1 + v2;
    float s2 = v0*v0 + v1*v1 + v2*v2;
    #pragma unroll
    for (int o = 16; o > 0; o >>= 1) {
        s  += __shfl_xor_sync(0xffffffffu, s,  o);
        s2 += __shfl_xor_sync(0xffffffffu, s2, o);
    }
    __shared__ float red0[8], red1[8];
    __shared__ float stat[2];
    int w = t >> 5, l = t & 31;
    if (l == 0) { red0[w] = s; red1[w] = s2; }
    __syncthreads();
    if (t == 0) {
        float ts = 0.f, ts2 = 0.f;
        #pragma unroll
        for (int i = 0; i < 8; i++) { ts += red0[i]; ts2 += red1[i]; }
        float mu  = ts * (1.0f / HID);
        float var = ts2 * (1.0f / HID) - mu * mu;
        stat[0] = mu;
        stat[1] = rsqrtf(var + 1e-5f);
    }
    __syncthreads();
    float mu = stat[0], inv = stat[1];
    float* o = g_xn + (size_t)row * HID;
    o[t]       = (v0 - mu) * inv * gam[t]       + bet[t];
    o[t + 256] = (v1 - mu) * inv * gam[t + 256] + bet[t + 256];
    o[t + 512] = (v2 - mu) * inv * gam[t + 512] + bet[t + 512];
}

// ---------------------------------------------------------------- Transpose (R x C -> C x R), dims % 32 == 0
// Also rounds weights to tf32 (rna) so the B operand is cleanly rounded.
__global__ void transpose_kernel(const float* __restrict__ in, float* __restrict__ out,
                                 int R, int C)
{
    __shared__ float tile[32][33];
    int bx = blockIdx.x * 32, by = blockIdx.y * 32;
    int tx = threadIdx.x, ty = threadIdx.y;
    #pragma unroll
    for (int i = 0; i < 32; i += 8)
        tile[ty + i][tx] = in[(size_t)(by + ty + i) * C + bx + tx];
    __syncthreads();
    #pragma unroll
    for (int i = 0; i < 32; i += 8)
        out[(size_t)(bx + ty + i) * R + by + tx] = f2tf32_rna(tile[tx][ty + i]);
}

// ---------------------------------------------------------------- HMMA tf32 GEMM
// 128x128 CTA tile, 4 warps (128 threads), 64x64 warp tile (4 mt x 8 nt mma).
// Halves smem fragment re-reads vs 8-warp/64x32 layout (crossbar was binding).
// C[128m x 128n] = epi( A[M,K](lda) @ Bt[n, K](ldb)^T + bias [+ R] )
// epi: 0 = none, 1 = gelu. K % 32 == 0. M % 128 == 0, N % 128 == 0.
__global__ __launch_bounds__(128, 2)
void tgemm_kernel(const float* __restrict__ A, int lda,
                  const float* __restrict__ Bt, int ldb,
                  const float* __restrict__ bias,
                  const float* __restrict__ R,
                  float* __restrict__ C, int ldc,
                  int K, int epi)
{
    extern __shared__ float sm[];
    uint32_t sbase = smem_u32(sm);

    int t = threadIdx.x;
    int wid = t >> 5, lane = t & 31;
    int warp_m = (wid >> 1) * 64, warp_n = (wid & 1) * 64;
    int bm = blockIdx.y * 128, bn = blockIdx.x * 128;
    int r = lane >> 2, c = lane & 3;

    const float* Ag = A  + (size_t)bm * lda;
    const float* Bg = Bt + (size_t)bn * ldb;

    float acc[32][4];                 // [mt*8+nt][4]
    #pragma unroll
    for (int i = 0; i < 32; i++)
        #pragma unroll
        for (int j = 0; j < 4; j++) acc[i][j] = 0.f;

    // chunk mapping: 1024 pieces per tile, 128 threads -> 8 pieces each
    int cm[8], ck[8];
    #pragma unroll
    for (int i = 0; i < 8; i++) {
        int id = t + i * 128;
        cm[i] = id >> 3;              // row 0..127
        ck[i] = (id & 7) * 4;         // float offset within 32-float row
    }

    auto load_stage = [&](int buf, int kbase) {
        uint32_t ab = sbase + (uint32_t)buf * STAGE_BYTES;
        uint32_t bb = ab + TILE_BYTES;
        #pragma unroll
        for (int i = 0; i < 8; i++) {
            cp_async16(ab + (uint32_t)(cm[i] * ASTR + ck[i]) * 4u,
                       Ag + (size_t)cm[i] * lda + kbase + ck[i]);
            cp_async16(bb + (uint32_t)(cm[i] * ASTR + ck[i]) * 4u,
                       Bg + (size_t)cm[i] * ldb + kbase + ck[i]);
        }
    };

    int S = K / 32;
    load_stage(0, 0);
    cp_commit();

    for (int s = 0; s < S; s++) {
        int buf = s & 1;
        if (s + 1 < S) {
            load_stage(buf ^ 1, (s + 1) * 32);
            cp_commit();
            cp_wait1();
        } else {
            cp_wait0();
        }
        __syncthreads();

        uint32_t ab = sbase + (uint32_t)buf * STAGE_BYTES;
        uint32_t bb = ab + TILE_BYTES;
        #pragma unroll
        for (int ks = 0; ks < 4; ks++) {
            int k0 = ks * 8;
            uint32_t af[4][4];
            #pragma unroll
            for (int mt = 0; mt < 4; mt++) {
                uint32_t base = ab + (uint32_t)((warp_m + mt * 16 + r) * ASTR + k0 + c) * 4u;
                af[mt][0] = lds32(base);
                af[mt][1] = lds32(base + 8u * ASTR * 4u);
                af[mt][2] = lds32(base + 16u);
                af[mt][3] = lds32(base + 8u * ASTR * 4u + 16u);
            }
            uint32_t bf[8][2];
            #pragma unroll
            for (int nt = 0; nt < 8; nt++) {
                uint32_t base = bb + (uint32_t)((warp_n + nt * 8 + r) * ASTR + k0 + c) * 4u;
                bf[nt][0] = lds32(base);
                bf[nt][1] = lds32(base + 16u);
            }
            #pragma unroll
            for (int mt = 0; mt < 4; mt++)
                #pragma unroll
                for (int nt = 0; nt < 8; nt++)
                    mma_tf32(acc[mt * 8 + nt], af[mt], bf[nt]);
        }
        __syncthreads();
    }

    // epilogue: fragment map c0:(r,2c) c1:(r,2c+1) c2:(r+8,2c) c3:(r+8,2c+1)
    #pragma unroll
    for (int mt = 0; mt < 4; mt++) {
        #pragma unroll
        for (int nt = 0; nt < 8; nt++) {
            float* a4 = acc[mt * 8 + nt];
            int gm0 = bm + warp_m + mt * 16 + r;
            int gn  = bn + warp_n + nt * 8 + c * 2;
            float bx = bias[gn], by = bias[gn + 1];
            #pragma unroll
            for (int half = 0; half < 2; half++) {
                int gm = gm0 + half * 8;
                float vx = a4[half * 2 + 0] + bx;
                float vy = a4[half * 2 + 1] + by;
                if (R) {
                    const float* rp = R + (size_t)gm * ldc + gn;
                    vx += rp[0]; vy += rp[1];
                }
                if (epi == 1) { vx = gelu_f(vx); vy = gelu_f(vy); }
                *(float2*)(C + (size_t)gm * ldc + gn) = make_float2(vx, vy);
            }
        }
    }
}

// ---------------------------------------------------------------- Attention (unchanged from R7)
__global__ __launch_bounds__(256, 2)
void attn_kernel(const float* __restrict__ pos_sin,
                 const float* __restrict__ pos_cos,
                 const int* __restrict__ lenp)
{
    __shared__ float4 ks[32][16];
    __shared__ float4 vs[32][16];

    int bx = blockIdx.x;
    int c  = bx >> 1, qh = bx & 1;
    int h  = blockIdx.y;
    int t  = threadIdx.x;
    int w  = t >> 5;
    int ql = t >> 1;
    int seg = t & 1;
    int qtok = c * CH + qh * 128 + ql;
    unsigned lm   = ~((unsigned)(*lenp) - 1u);
    unsigned qseq = (unsigned)qtok & lm;

    const float SCALE = 0.125f;
    float q[32];
    {
        const float4* qp = (const float4*)(g_qkv + (size_t)qtok * QKVW + h * DH + seg * 32);
        const float4* sp = (const float4*)(pos_sin + (size_t)qtok * DH + seg * 32);
        const float4* cp = (const float4*)(pos_cos + (size_t)qtok * DH + seg * 32);
        #pragma unroll
        for (int i = 0; i < 8; i++) {
            float4 xv = qp[i], sv = sp[i], cv = cp[i];
            q[4*i + 0] = (xv.x * cv.x - xv.y * sv.x) * SCALE;
            q[4*i + 1] = (xv.y * cv.y + xv.x * sv.y) * SCALE;
            q[4*i + 2] = (xv.z * cv.z - xv.w * sv.z) * SCALE;
            q[4*i + 3] = (xv.w * cv.w + xv.z * sv.w) * SCALE;
        }
    }

    float o[32];
    #pragma unroll
    for (int d = 0; d < 32; d++) o[d] = 0.f;
    float m = -FLT_MAX, lsum = 0.f;

    int kt_beg = qh * 4, kt_end = qh * 4 + 12;
    if (c == 0 && kt_beg < 8) kt_beg = 8;

    for (int kt = kt_beg; kt < kt_end; kt++) {
        int kbase = c * CH - CH + kt * 32;
        #pragma unroll
        for (int i = 0; i < 2; i++) {
            int f = t * 2 + i;
            int row = f >> 4, col4 = f & 15;
            int ktok = kbase + row;
            const float4* kp = (const float4*)(g_qkv + (size_t)ktok * QKVW + HID     + h * DH) + col4;
            const float4* vp = (const float4*)(g_qkv + (size_t)ktok * QKVW + 2 * HID + h * DH) + col4;
            float4 kv = *kp, vv = *vp;
            float4 svv = ((const float4*)(pos_sin + (size_t)ktok * DH))[col4];
            float4 cvv = ((const float4*)(pos_cos + (size_t)ktok * DH))[col4];
            float4 kr;
            kr.x = kv.x * cvv.x - kv.y * svv.x;
            kr.y = kv.y * cvv.y + kv.x * svv.y;
            kr.z = kv.z * cvv.z - kv.w * svv.z;
            kr.w = kv.w * cvv.w + kv.z * svv.w;
            ks[row][col4] = kr;
            vs[row][col4] = vv;
        }
        __syncthreads();

        int qmin = c * CH + qh * 128 + w * 16;
        bool active = (kbase <= qmin + 15) && (qmin - (kbase + 31) < WIN);
        if (active) {
            #pragma unroll
            for (int half = 0; half < 2; half++) {
                float s[16];
                float tmax = -FLT_MAX;
                bool any = false;
                #pragma unroll
                for (int j = 0; j < 16; j++) {
                    int row = half * 16 + j;
                    float dot = 0.f;
                    #pragma unroll
                    for (int dd = 0; dd < 8; dd++) {
                        float4 kk = ks[row][seg * 8 + dd];
                        dot += q[4*dd + 0] * kk.x + q[4*dd + 1] * kk.y
                             + q[4*dd + 2] * kk.z + q[4*dd + 3] * kk.w;
                    }
                    dot += __shfl_xor_sync(0xffffffffu, dot, 1);
                    int ktok = kbase + row;
                    int d = qtok - ktok;
                    bool valid = (d >= 0) && (d < WIN) && (((unsigned)ktok & lm) == qseq);
                    s[j] = valid ? dot : -FLT_MAX;
                    any |= valid;
                    tmax = fmaxf(tmax, s[j]);
                }
                if (any) {
                    float mnew = fmaxf(m, tmax);
                    float corr = __expf(m - mnew);
                    lsum *= corr;
                    #pragma unroll
                    for (int d = 0; d < 32; d++) o[d] *= corr;
                    #pragma unroll
                    for (int j = 0; j < 16; j++) {
                        float p = __expf(s[j] - mnew);
                        lsum += p;
                        int row = half * 16 + j;
                        #pragma unroll
                        for (int dd = 0; dd < 8; dd++) {
                            float4 vv = vs[row][seg * 8 + dd];
                            o[4*dd + 0] += p * vv.x; o[4*dd + 1] += p * vv.y;
                            o[4*dd + 2] += p * vv.z; o[4*dd + 3] += p * vv.w;
                        }
                    }
                    m = mnew;
                }
            }
        }
        __syncthreads();
    }

    float inv = 1.0f / lsum;
    float4* op = (float4*)(g_comb + (size_t)qtok * COMBW + h * DH + seg * 32);
    #pragma unroll
    for (int dd = 0; dd < 8; dd++)
        op[dd] = make_float4(o[4*dd + 0] * inv, o[4*dd + 1] * inv,
                             o[4*dd + 2] * inv, o[4*dd + 3] * inv);
}

// ---------------------------------------------------------------- launch
extern "C" void kernel_launch(void* const* d_in, const int* in_sizes, int n_in,
                              void* d_out, int out_size)
{
    (void)in_sizes; (void)n_in; (void)out_size;
    const float* x        = (const float*)d_in[0];
    const float* pos_sin  = (const float*)d_in[2];
    const float* pos_cos  = (const float*)d_in[3];
    const float* ln_scale = (const float*)d_in[4];
    const float* ln_off   = (const float*)d_in[5];
    const float* w_in     = (const float*)d_in[6];
    const float* b_in     = (const float*)d_in[7];
    const float* w_out    = (const float*)d_in[8];
    const float* b_out    = (const float*)d_in[9];
    const int*   lenp     = (const int*)d_in[10];
    float* out = (float*)d_out;

    static float *p_xn = nullptr, *p_qkv = nullptr, *p_comb = nullptr,
                 *p_wt1 = nullptr, *p_wt2 = nullptr;
    static cudaStream_t s1 = nullptr;
    static cudaEvent_t e0 = nullptr, eT = nullptr, eLN = nullptr, eF = nullptr;
    if (!p_xn) {
        cudaGetSymbolAddress((void**)&p_xn,   g_xn);
        cudaGetSymbolAddress((void**)&p_qkv,  g_qkv);
        cudaGetSymbolAddress((void**)&p_comb, g_comb);
        cudaGetSymbolAddress((void**)&p_wt1,  g_wt1);
        cudaGetSymbolAddress((void**)&p_wt2,  g_wt2);
        cudaFuncSetAttribute(tgemm_kernel,
                             cudaFuncAttributeMaxDynamicSharedMemorySize, DSMEM_BYTES);
        cudaStreamCreateWithFlags(&s1, cudaStreamNonBlocking);
        cudaEventCreateWithFlags(&e0,  cudaEventDisableTiming);
        cudaEventCreateWithFlags(&eT,  cudaEventDisableTiming);
        cudaEventCreateWithFlags(&eLN, cudaEventDisableTiming);
        cudaEventCreateWithFlags(&eF,  cudaEventDisableTiming);
    }

    // fork s1 from the (captured) default stream
    cudaEventRecord(e0, 0);
    cudaStreamWaitEvent(s1, e0, 0);

    // s1: weight transposes (+tf32 round); s0: layernorm
    transpose_kernel<<<dim3(MIDW / 32, HID / 32),   dim3(32, 8), 0, s1>>>(w_in,  p_wt1, HID,   MIDW);
    transpose_kernel<<<dim3(HID / 32,  COMBW / 32), dim3(32, 8), 0, s1>>>(w_out, p_wt2, COMBW, HID);
    ln_kernel<<<NTOK, 256>>>(x, ln_scale, ln_off);
    cudaEventRecord(eLN, 0);

    // s0: QKV GEMM (needs wt1 from s1)
    cudaEventRecord(eT, s1);
    cudaStreamWaitEvent(0, eT, 0);
    tgemm_kernel<<<dim3(QKVW / 128, NTOK / 128), 128, DSMEM_BYTES>>>(
        p_xn, HID, p_wt1, HID, b_in, nullptr, p_qkv, QKVW, HID, 0);

    // s1: FF GEMM + gelu (needs ln; wt1 already on s1) — overlaps QKV + attn
    cudaStreamWaitEvent(s1, eLN, 0);
    tgemm_kernel<<<dim3(INTER / 128, NTOK / 128), 128, DSMEM_BYTES, s1>>>(
        p_xn, HID, p_wt1 + (size_t)QKVW * HID, HID, b_in + QKVW, nullptr,
        p_comb + HID, COMBW, HID, 1);
    cudaEventRecord(eF, s1);

    // s0: attention (needs qkv) -> comb[:, :768]
    attn_kernel<<<dim3(NCHUNK * 2, NH), 256>>>(pos_sin, pos_cos, lenp);

    // join, then s0: out = xn + comb @ w_out + b_out
    cudaStreamWaitEvent(0, eF, 0);
    tgemm_kernel<<<dim3(HID / 128, NTOK / 128), 128, DSMEM_BYTES>>>(
        p_comb, COMBW, p_wt2, COMBW, b_out, p_xn, out, HID, COMBW, 0);
}

// round 10
// speedup vs baseline: 2.3820x; 1.0038x over previous
#include <cuda_runtime.h>
#include <cfloat>
#include <cstddef>
#include <cstdint>

#define HID   768
#define INTER 3072
#define NH    12
#define DH    64
#define NTOK  16384
#define WIN   256
#define CH    256
#define MIDW  (3*HID + INTER)   // 5376
#define QKVW  (3*HID)           // 2304
#define COMBW (HID + INTER)     // 3840
#define NCHUNK (NTOK / CH)      // 64

#define ASTR 36                       // smem row stride in floats (pad 4)
#define TILE_BYTES (128 * ASTR * 4)   // 18432 per operand tile
#define STAGE_BYTES (2 * TILE_BYTES)  // A + B
#define DSMEM_BYTES (2 * STAGE_BYTES) // 73728, double buffered

// Scratch (device globals: allocation inside kernel_launch is forbidden)
__device__ float g_xn  [(size_t)NTOK * HID];     //  50 MB
__device__ float g_qkv [(size_t)NTOK * QKVW];    // 151 MB
__device__ float g_comb[(size_t)NTOK * COMBW];   // 252 MB
__device__ float g_wt1 [(size_t)MIDW * HID];     //  16.5 MB  w_in^T  [5376][768]
__device__ float g_wt2 [(size_t)HID * COMBW];    //  11.8 MB  w_out^T [768][3840]

// ---------------------------------------------------------------- helpers
__device__ __forceinline__ uint32_t smem_u32(const void* p) {
    uint32_t a;
    asm("{ .reg .u64 t; cvta.to.shared.u64 t, %1; cvt.u32.u64 %0, t; }"
        : "=r"(a) : "l"(p));
    return a;
}
__device__ __forceinline__ float f2tf32_rna(float x) {
    uint32_t u;
    asm("cvt.rna.tf32.f32 %0, %1;" : "=r"(u) : "f"(x));
    return __uint_as_float(u);
}
__device__ __forceinline__ void cp_async16(uint32_t dst, const void* src) {
    asm volatile("cp.async.cg.shared.global [%0], [%1], 16;"
                 :: "r"(dst), "l"(src) : "memory");
}
__device__ __forceinline__ void cp_commit() {
    asm volatile("cp.async.commit_group;" ::: "memory");
}
__device__ __forceinline__ void cp_wait0() {
    asm volatile("cp.async.wait_group 0;" ::: "memory");
}
__device__ __forceinline__ uint32_t lds32(uint32_t addr) {
    uint32_t v;
    asm volatile("ld.shared.b32 %0, [%1];" : "=r"(v) : "r"(addr));
    return v;
}
__device__ __forceinline__ void mma_tf32(float* d, const uint32_t* a, const uint32_t* b) {
    asm volatile(
        "mma.sync.aligned.m16n8k8.row.col.f32.tf32.tf32.f32 "
        "{%0,%1,%2,%3}, {%4,%5,%6,%7}, {%8,%9}, {%0,%1,%2,%3};"
        : "+f"(d[0]), "+f"(d[1]), "+f"(d[2]), "+f"(d[3])
        : "r"(a[0]), "r"(a[1]), "r"(a[2]), "r"(a[3]), "r"(b[0]), "r"(b[1]));
}

// ---- packed f32x2 (sm_100+ baseline PTX; FFMA2 path) ----
__device__ __forceinline__ unsigned long long pack2(float lo, float hi) {
    unsigned long long r;
    asm("mov.b64 %0, {%1, %2};" : "=l"(r) : "f"(lo), "f"(hi));
    return r;
}
__device__ __forceinline__ void unpack2(unsigned long long v, float& lo, float& hi) {
    asm("mov.b64 {%0, %1}, %2;" : "=f"(lo), "=f"(hi) : "l"(v));
}
__device__ __forceinline__ void fma2(unsigned long long& d,
                                     unsigned long long a, unsigned long long b) {
    asm("fma.rn.f32x2 %0, %1, %2, %0;" : "+l"(d) : "l"(a), "l"(b));
}
__device__ __forceinline__ unsigned long long mul2(unsigned long long a,
                                                   unsigned long long b) {
    unsigned long long r;
    asm("mul.rn.f32x2 %0, %1, %2;" : "=l"(r) : "l"(a), "l"(b));
    return r;
}

// ---------------------------------------------------------------- GELU (tanh approx = jax default)
__device__ __forceinline__ float gelu_f(float x) {
    float x3 = x * x * x;
    return 0.5f * x * (1.0f + tanhf(0.7978845608028654f * (x + 0.044715f * x3)));
}

// ---------------------------------------------------------------- LayerNorm
__global__ void ln_kernel(const float* __restrict__ x,
                          const float* __restrict__ gam,
                          const float* __restrict__ bet)
{
    int row = blockIdx.x;
    int t   = threadIdx.x;
    const float* xr = x + (size_t)row * HID;
    float v0 = xr[t], v1 = xr[t + 256], v2 = xr[t + 512];
    float s  = v0 + v1 + v2;
    float s2 = v0*v0 + v1*v1 + v2*v2;
    #pragma unroll
    for (int o = 16; o > 0; o >>= 1) {
        s  += __shfl_xor_sync(0xffffffffu, s,  o);
        s2 += __shfl_xor_sync(0xffffffffu, s2, o);
    }
    __shared__ float red0[8], red1[8];
    __shared__ float stat[2];
    int w = t >> 5, l = t & 31;
    if (l == 0) { red0[w] = s; red1[w] = s2; }
    __syncthreads();
    if (t == 0) {
        float ts = 0.f, ts2 = 0.f;
        #pragma unroll
        for (int i = 0; i < 8; i++) { ts += red0[i]; ts2 += red1[i]; }
        float mu  = ts * (1.0f / HID);
        float var = ts2 * (1.0f / HID) - mu * mu;
        stat[0] = mu;
        stat[1] = rsqrtf(var + 1e-5f);
    }
    __syncthreads();
    float mu = stat[0], inv = stat[1];
    float* o = g_xn + (size_t)row * HID;
    o[t]       = (v0 - mu) * inv * gam[t]       + bet[t];
    o[t + 256] = (v1 - mu) * inv * gam[t + 256] + bet[t + 256];
    o[t + 512] = (v2 - mu) * inv * gam[t + 512] + bet[t + 512];
}

// ---------------------------------------------------------------- Transpose (R x C -> C x R), dims % 32 == 0
__global__ void transpose_kernel(const float* __restrict__ in, float* __restrict__ out,
                                 int R, int C)
{
    __shared__ float tile[32][33];
    int bx = blockIdx.x * 32, by = blockIdx.y * 32;
    int tx = threadIdx.x, ty = threadIdx.y;
    #pragma unroll
    for (int i = 0; i < 32; i += 8)
        tile[ty + i][tx] = in[(size_t)(by + ty + i) * C + bx + tx];
    __syncthreads();
    #pragma unroll
    for (int i = 0; i < 32; i += 8)
        out[(size_t)(bx + ty + i) * R + by + tx] = f2tf32_rna(tile[tx][ty + i]);
}

// ---------------------------------------------------------------- HMMA tf32 GEMM
// 128x128 CTA tile, 4 warps, 64x64 warp tile. Single __syncthreads per
// K-stage: wait -> sync -> issue next cp.async -> compute (buffer written
// after the sync was last read at stage s-1, so no trailing barrier needed).
__global__ __launch_bounds__(128, 2)
void tgemm_kernel(const float* __restrict__ A, int lda,
                  const float* __restrict__ Bt, int ldb,
                  const float* __restrict__ bias,
                  const float* __restrict__ R,
                  float* __restrict__ C, int ldc,
                  int K, int epi)
{
    extern __shared__ float sm[];
    uint32_t sbase = smem_u32(sm);

    int t = threadIdx.x;
    int wid = t >> 5, lane = t & 31;
    int warp_m = (wid >> 1) * 64, warp_n = (wid & 1) * 64;
    int bm = blockIdx.y * 128, bn = blockIdx.x * 128;
    int r = lane >> 2, c = lane & 3;

    const float* Ag = A  + (size_t)bm * lda;
    const float* Bg = Bt + (size_t)bn * ldb;

    float acc[32][4];                 // [mt*8+nt][4]
    #pragma unroll
    for (int i = 0; i < 32; i++)
        #pragma unroll
        for (int j = 0; j < 4; j++) acc[i][j] = 0.f;

    int cm[8], ck[8];
    #pragma unroll
    for (int i = 0; i < 8; i++) {
        int id = t + i * 128;
        cm[i] = id >> 3;              // row 0..127
        ck[i] = (id & 7) * 4;         // float offset within 32-float row
    }

    auto load_stage = [&](int buf, int kbase) {
        uint32_t ab = sbase + (uint32_t)buf * STAGE_BYTES;
        uint32_t bb = ab + TILE_BYTES;
        #pragma unroll
        for (int i = 0; i < 8; i++) {
            cp_async16(ab + (uint32_t)(cm[i] * ASTR + ck[i]) * 4u,
                       Ag + (size_t)cm[i] * lda + kbase + ck[i]);
            cp_async16(bb + (uint32_t)(cm[i] * ASTR + ck[i]) * 4u,
                       Bg + (size_t)cm[i] * ldb + kbase + ck[i]);
        }
    };

    int S = K / 32;
    load_stage(0, 0);
    cp_commit();

    for (int s = 0; s < S; s++) {
        cp_wait0();                  // only one group ever in flight
        __syncthreads();             // data ready + everyone past stage s-1 reads
        if (s + 1 < S) {
            load_stage((s + 1) & 1, (s + 1) * 32);
            cp_commit();
        }

        uint32_t ab = sbase + (uint32_t)(s & 1) * STAGE_BYTES;
        uint32_t bb = ab + TILE_BYTES;
        #pragma unroll
        for (int ks = 0; ks < 4; ks++) {
            int k0 = ks * 8;
            uint32_t af[4][4];
            #pragma unroll
            for (int mt = 0; mt < 4; mt++) {
                uint32_t base = ab + (uint32_t)((warp_m + mt * 16 + r) * ASTR + k0 + c) * 4u;
                af[mt][0] = lds32(base);
                af[mt][1] = lds32(base + 8u * ASTR * 4u);
                af[mt][2] = lds32(base + 16u);
                af[mt][3] = lds32(base + 8u * ASTR * 4u + 16u);
            }
            uint32_t bf[8][2];
            #pragma unroll
            for (int nt = 0; nt < 8; nt++) {
                uint32_t base = bb + (uint32_t)((warp_n + nt * 8 + r) * ASTR + k0 + c) * 4u;
                bf[nt][0] = lds32(base);
                bf[nt][1] = lds32(base + 16u);
            }
            #pragma unroll
            for (int mt = 0; mt < 4; mt++)
                #pragma unroll
                for (int nt = 0; nt < 8; nt++)
                    mma_tf32(acc[mt * 8 + nt], af[mt], bf[nt]);
        }
        // no trailing sync: next iteration's wait+sync provides the hazard fence
    }

    // epilogue: fragment map c0:(r,2c) c1:(r,2c+1) c2:(r+8,2c) c3:(r+8,2c+1)
    #pragma unroll
    for (int mt = 0; mt < 4; mt++) {
        #pragma unroll
        for (int nt = 0; nt < 8; nt++) {
            float* a4 = acc[mt * 8 + nt];
            int gm0 = bm + warp_m + mt * 16 + r;
            int gn  = bn + warp_n + nt * 8 + c * 2;
            float bx = bias[gn], by = bias[gn + 1];
            #pragma unroll
            for (int half = 0; half < 2; half++) {
                int gm = gm0 + half * 8;
                float vx = a4[half * 2 + 0] + bx;
                float vy = a4[half * 2 + 1] + by;
                if (R) {
                    const float* rp = R + (size_t)gm * ldc + gn;
                    vx += rp[0]; vy += rp[1];
                }
                if (epi == 1) { vx = gelu_f(vx); vy = gelu_f(vy); }
                *(float2*)(C + (size_t)gm * ldc + gn) = make_float2(vx, vy);
            }
        }
    }
}

// ---------------------------------------------------------------- Attention
// Lane-pair split + packed f32x2 math: each thread owns 32 of 64 dims, dots
// and o[] accumulate in 2-wide packed FMAs (halves FFMA issue count).
__global__ __launch_bounds__(256, 2)
void attn_kernel(const float* __restrict__ pos_sin,
                 const float* __restrict__ pos_cos,
                 const int* __restrict__ lenp)
{
    __shared__ float4 ks[32][16];
    __shared__ float4 vs[32][16];

    int bx = blockIdx.x;
    int c  = bx >> 1, qh = bx & 1;
    int h  = blockIdx.y;
    int t  = threadIdx.x;
    int w  = t >> 5;
    int ql = t >> 1;
    int seg = t & 1;
    int qtok = c * CH + qh * 128 + ql;
    unsigned lm   = ~((unsigned)(*lenp) - 1u);
    unsigned qseq = (unsigned)qtok & lm;

    const float SCALE = 0.125f;
    unsigned long long q2[16];
    {
        const float4* qp = (const float4*)(g_qkv + (size_t)qtok * QKVW + h * DH + seg * 32);
        const float4* sp = (const float4*)(pos_sin + (size_t)qtok * DH + seg * 32);
        const float4* cp = (const float4*)(pos_cos + (size_t)qtok * DH + seg * 32);
        #pragma unroll
        for (int i = 0; i < 8; i++) {
            float4 xv = qp[i], sv = sp[i], cv = cp[i];
            float a0 = (xv.x * cv.x - xv.y * sv.x) * SCALE;
            float a1 = (xv.y * cv.y + xv.x * sv.y) * SCALE;
            float a2 = (xv.z * cv.z - xv.w * sv.z) * SCALE;
            float a3 = (xv.w * cv.w + xv.z * sv.w) * SCALE;
            q2[2*i + 0] = pack2(a0, a1);
            q2[2*i + 1] = pack2(a2, a3);
        }
    }

    unsigned long long o2[16];
    #pragma unroll
    for (int d = 0; d < 16; d++) o2[d] = 0ull;
    float m = -FLT_MAX, lsum = 0.f;

    int kt_beg = qh * 4, kt_end = qh * 4 + 12;
    if (c == 0 && kt_beg < 8) kt_beg = 8;

    for (int kt = kt_beg; kt < kt_end; kt++) {
        int kbase = c * CH - CH + kt * 32;
        #pragma unroll
        for (int i = 0; i < 2; i++) {
            int f = t * 2 + i;
            int row = f >> 4, col4 = f & 15;
            int ktok = kbase + row;
            const float4* kp = (const float4*)(g_qkv + (size_t)ktok * QKVW + HID     + h * DH) + col4;
            const float4* vp = (const float4*)(g_qkv + (size_t)ktok * QKVW + 2 * HID + h * DH) + col4;
            float4 kv = *kp, vv = *vp;
            float4 svv = ((const float4*)(pos_sin + (size_t)ktok * DH))[col4];
            float4 cvv = ((const float4*)(pos_cos + (size_t)ktok * DH))[col4];
            float4 kr;
            kr.x = kv.x * cvv.x - kv.y * svv.x;
            kr.y = kv.y * cvv.y + kv.x * svv.y;
            kr.z = kv.z * cvv.z - kv.w * svv.z;
            kr.w = kv.w * cvv.w + kv.z * svv.w;
            ks[row][col4] = kr;
            vs[row][col4] = vv;
        }
        __syncthreads();

        int qmin = c * CH + qh * 128 + w * 16;
        bool active = (kbase <= qmin + 15) && (qmin - (kbase + 31) < WIN);
        if (active) {
            #pragma unroll
            for (int half = 0; half < 2; half++) {
                float s[16];
                float tmax = -FLT_MAX;
                bool any = false;
                #pragma unroll
                for (int j = 0; j < 16; j++) {
                    int row = half * 16 + j;
                    unsigned long long dot2 = 0ull;
                    const ulonglong2* krow = (const ulonglong2*)&ks[row][seg * 8];
                    #pragma unroll
                    for (int dd = 0; dd < 8; dd++) {
                        ulonglong2 kk = krow[dd];
                        fma2(dot2, q2[2*dd + 0], kk.x);
                        fma2(dot2, q2[2*dd + 1], kk.y);
                    }
                    float lo, hi;
                    unpack2(dot2, lo, hi);
                    float dot = lo + hi;
                    dot += __shfl_xor_sync(0xffffffffu, dot, 1);
                    int ktok = kbase + row;
                    int d = qtok - ktok;
                    bool valid = (d >= 0) && (d < WIN) && (((unsigned)ktok & lm) == qseq);
                    s[j] = valid ? dot : -FLT_MAX;
                    any |= valid;
                    tmax = fmaxf(tmax, s[j]);
                }
                if (any) {
                    float mnew = fmaxf(m, tmax);
                    float corr = __expf(m - mnew);
                    lsum *= corr;
                    unsigned long long corr2 = pack2(corr, corr);
                    #pragma unroll
                    for (int d = 0; d < 16; d++) o2[d] = mul2(o2[d], corr2);
                    #pragma unroll
                    for (int j = 0; j < 16; j++) {
                        float p = __expf(s[j] - mnew);
                        lsum += p;
                        unsigned long long pp = pack2(p, p);
                        int row = half * 16 + j;
                        const ulonglong2* vrow = (const ulonglong2*)&vs[row][seg * 8];
                        #pragma unroll
                        for (int dd = 0; dd < 8; dd++) {
                            ulonglong2 vv = vrow[dd];
                            fma2(o2[2*dd + 0], pp, vv.x);
                            fma2(o2[2*dd + 1], pp, vv.y);
                        }
                    }
                    m = mnew;
                }
            }
        }
        __syncthreads();
    }

    float inv = 1.0f / lsum;
    unsigned long long inv2 = pack2(inv, inv);
    ulonglong2* op = (ulonglong2*)(g_comb + (size_t)qtok * COMBW + h * DH + seg * 32);
    #pragma unroll
    for (int i = 0; i < 8; i++) {
        ulonglong2 v;
        v.x = mul2(o2[2*i + 0], inv2);
        v.y = mul2(o2[2*i + 1], inv2);
        op[i] = v;
    }
}

// ---------------------------------------------------------------- launch
extern "C" void kernel_launch(void* const* d_in, const int* in_sizes, int n_in,
                              void* d_out, int out_size)
{
    (void)in_sizes; (void)n_in; (void)out_size;
    const float* x        = (const float*)d_in[0];
    const float* pos_sin  = (const float*)d_in[2];
    const float* pos_cos  = (const float*)d_in[3];
    const float* ln_scale = (const float*)d_in[4];
    const float* ln_off   = (const float*)d_in[5];
    const float* w_in     = (const float*)d_in[6];
    const float* b_in     = (const float*)d_in[7];
    const float* w_out    = (const float*)d_in[8];
    const float* b_out    = (const float*)d_in[9];
    const int*   lenp     = (const int*)d_in[10];
    float* out = (float*)d_out;

    static float *p_xn = nullptr, *p_qkv = nullptr, *p_comb = nullptr,
                 *p_wt1 = nullptr, *p_wt2 = nullptr;
    static cudaStream_t s1 = nullptr;
    static cudaEvent_t e0 = nullptr, eT = nullptr, eLN = nullptr, eF = nullptr;
    if (!p_xn) {
        cudaGetSymbolAddress((void**)&p_xn,   g_xn);
        cudaGetSymbolAddress((void**)&p_qkv,  g_qkv);
        cudaGetSymbolAddress((void**)&p_comb, g_comb);
        cudaGetSymbolAddress((void**)&p_wt1,  g_wt1);
        cudaGetSymbolAddress((void**)&p_wt2,  g_wt2);
        cudaFuncSetAttribute(tgemm_kernel,
                             cudaFuncAttributeMaxDynamicSharedMemorySize, DSMEM_BYTES);
        cudaStreamCreateWithFlags(&s1, cudaStreamNonBlocking);
        cudaEventCreateWithFlags(&e0,  cudaEventDisableTiming);
        cudaEventCreateWithFlags(&eT,  cudaEventDisableTiming);
        cudaEventCreateWithFlags(&eLN, cudaEventDisableTiming);
        cudaEventCreateWithFlags(&eF,  cudaEventDisableTiming);
    }

    // fork s1 from the (captured) default stream
    cudaEventRecord(e0, 0);
    cudaStreamWaitEvent(s1, e0, 0);

    // s1: weight transposes (+tf32 round); s0: layernorm
    transpose_kernel<<<dim3(MIDW / 32, HID / 32),   dim3(32, 8), 0, s1>>>(w_in,  p_wt1, HID,   MIDW);
    transpose_kernel<<<dim3(HID / 32,  COMBW / 32), dim3(32, 8), 0, s1>>>(w_out, p_wt2, COMBW, HID);
    ln_kernel<<<NTOK, 256>>>(x, ln_scale, ln_off);
    cudaEventRecord(eLN, 0);

    // s0: QKV GEMM (needs wt1 from s1)
    cudaEventRecord(eT, s1);
    cudaStreamWaitEvent(0, eT, 0);
    tgemm_kernel<<<dim3(QKVW / 128, NTOK / 128), 128, DSMEM_BYTES>>>(
        p_xn, HID, p_wt1, HID, b_in, nullptr, p_qkv, QKVW, HID, 0);

    // s1: FF GEMM + gelu (needs ln; wt1 already on s1) — overlaps QKV + attn
    cudaStreamWaitEvent(s1, eLN, 0);
    tgemm_kernel<<<dim3(INTER / 128, NTOK / 128), 128, DSMEM_BYTES, s1>>>(
        p_xn, HID, p_wt1 + (size_t)QKVW * HID, HID, b_in + QKVW, nullptr,
        p_comb + HID, COMBW, HID, 1);
    cudaEventRecord(eF, s1);

    // s0: attention (needs qkv) -> comb[:, :768]
    attn_kernel<<<dim3(NCHUNK * 2, NH), 256>>>(pos_sin, pos_cos, lenp);

    // join, then s0: out = xn + comb @ w_out + b_out
    cudaStreamWaitEvent(0, eF, 0);
    tgemm_kernel<<<dim3(HID / 128, NTOK / 128), 128, DSMEM_BYTES>>>(
        p_comb, COMBW, p_wt2, COMBW, b_out, p_xn, out, HID, COMBW, 0);
}

// round 11
// speedup vs baseline: 3.2362x; 1.3586x over previous
#include <cuda_runtime.h>
#include <cfloat>
#include <cstddef>
#include <cstdint>

#define HID   768
#define INTER 3072
#define NH    12
#define DH    64
#define NTOK  16384
#define WIN   256
#define CH    256
#define MIDW  (3*HID + INTER)   // 5376
#define QKVW  (3*HID)           // 2304
#define COMBW (HID + INTER)     // 3840
#define NCHUNK (NTOK / CH)      // 64

#define ASTR 36                       // gemm smem row stride in floats (pad 4)
#define TILE_BYTES (128 * ASTR * 4)   // 18432 per operand tile
#define STAGE_BYTES (2 * TILE_BYTES)  // A + B
#define DSMEM_BYTES (2 * STAGE_BYTES) // 73728, double buffered

#define AQ   68                       // attn Q/K/V smem row stride (floats)
#define PSTR 36                       // attn probs smem row stride
#define ATTN_SMEM ((128*AQ + 32*AQ + 32*AQ) * 4)   // 52224 B

// Scratch (device globals: allocation inside kernel_launch is forbidden)
__device__ float g_xn  [(size_t)NTOK * HID];     //  50 MB
__device__ float g_qkv [(size_t)NTOK * QKVW];    // 151 MB
__device__ float g_comb[(size_t)NTOK * COMBW];   // 252 MB
__device__ float g_wt1 [(size_t)MIDW * HID];     //  16.5 MB
__device__ float g_wt2 [(size_t)HID * COMBW];    //  11.8 MB
__device__ float g_qr  [(size_t)NH * NTOK * DH]; //  50 MB  RoPE'd+scaled Q [h][tok][d]
__device__ float g_kr  [(size_t)NH * NTOK * DH]; //  50 MB  RoPE'd K
__device__ float g_vr  [(size_t)NH * NTOK * DH]; //  50 MB  V

// ---------------------------------------------------------------- helpers
__device__ __forceinline__ uint32_t smem_u32(const void* p) {
    uint32_t a;
    asm("{ .reg .u64 t; cvta.to.shared.u64 t, %1; cvt.u32.u64 %0, t; }"
        : "=r"(a) : "l"(p));
    return a;
}
__device__ __forceinline__ float f2tf32_rna(float x) {
    uint32_t u;
    asm("cvt.rna.tf32.f32 %0, %1;" : "=r"(u) : "f"(x));
    return __uint_as_float(u);
}
__device__ __forceinline__ void cp_async16(uint32_t dst, const void* src) {
    asm volatile("cp.async.cg.shared.global [%0], [%1], 16;"
                 :: "r"(dst), "l"(src) : "memory");
}
__device__ __forceinline__ void cp_commit() {
    asm volatile("cp.async.commit_group;" ::: "memory");
}
__device__ __forceinline__ void cp_wait0() {
    asm volatile("cp.async.wait_group 0;" ::: "memory");
}
__device__ __forceinline__ uint32_t lds32(uint32_t addr) {
    uint32_t v;
    asm volatile("ld.shared.b32 %0, [%1];" : "=r"(v) : "r"(addr));
    return v;
}
__device__ __forceinline__ void mma_tf32(float* d, const uint32_t* a, const uint32_t* b) {
    asm volatile(
        "mma.sync.aligned.m16n8k8.row.col.f32.tf32.tf32.f32 "
        "{%0,%1,%2,%3}, {%4,%5,%6,%7}, {%8,%9}, {%0,%1,%2,%3};"
        : "+f"(d[0]), "+f"(d[1]), "+f"(d[2]), "+f"(d[3])
        : "r"(a[0]), "r"(a[1]), "r"(a[2]), "r"(a[3]), "r"(b[0]), "r"(b[1]));
}

// ---------------------------------------------------------------- GELU (tanh approx = jax default)
__device__ __forceinline__ float gelu_f(float x) {
    float x3 = x * x * x;
    return 0.5f * x * (1.0f + tanhf(0.7978845608028654f * (x + 0.044715f * x3)));
}

// ---------------------------------------------------------------- LayerNorm
__global__ void ln_kernel(const float* __restrict__ x,
                          const float* __restrict__ gam,
                          const float* __restrict__ bet)
{
    int row = blockIdx.x;
    int t   = threadIdx.x;
    const float* xr = x + (size_t)row * HID;
    float v0 = xr[t], v1 = xr[t + 256], v2 = xr[t + 512];
    float s  = v0 + v1 + v2;
    float s2 = v0*v0 + v1*v1 + v2*v2;
    #pragma unroll
    for (int o = 16; o > 0; o >>= 1) {
        s  += __shfl_xor_sync(0xffffffffu, s,  o);
        s2 += __shfl_xor_sync(0xffffffffu, s2, o);
    }
    __shared__ float red0[8], red1[8];
    __shared__ float stat[2];
    int w = t >> 5, l = t & 31;
    if (l == 0) { red0[w] = s; red1[w] = s2; }
    __syncthreads();
    if (t == 0) {
        float ts = 0.f, ts2 = 0.f;
        #pragma unroll
        for (int i = 0; i < 8; i++) { ts += red0[i]; ts2 += red1[i]; }
        float mu  = ts * (1.0f / HID);
        float var = ts2 * (1.0f / HID) - mu * mu;
        stat[0] = mu;
        stat[1] = rsqrtf(var + 1e-5f);
    }
    __syncthreads();
    float mu = stat[0], inv = stat[1];
    float* o = g_xn + (size_t)row * HID;
    o[t]       = (v0 - mu) * inv * gam[t]       + bet[t];
    o[t + 256] = (v1 - mu) * inv * gam[t + 256] + bet[t + 256];
    o[t + 512] = (v2 - mu) * inv * gam[t + 512] + bet[t + 512];
}

// ---------------------------------------------------------------- Transpose (R x C -> C x R), dims % 32 == 0
__global__ void transpose_kernel(const float* __restrict__ in, float* __restrict__ out,
                                 int R, int C)
{
    __shared__ float tile[32][33];
    int bx = blockIdx.x * 32, by = blockIdx.y * 32;
    int tx = threadIdx.x, ty = threadIdx.y;
    #pragma unroll
    for (int i = 0; i < 32; i += 8)
        tile[ty + i][tx] = in[(size_t)(by + ty + i) * C + bx + tx];
    __syncthreads();
    #pragma unroll
    for (int i = 0; i < 32; i += 8)
        out[(size_t)(bx + ty + i) * R + by + tx] = f2tf32_rna(tile[tx][ty + i]);
}

// ---------------------------------------------------------------- RoPE precompute
// g_qr/g_kr/g_vr[h][tok][d] <- RoPE(q)*scale, RoPE(k), v (all tf32-rounded)
__global__ void rope_kernel(const float* __restrict__ pos_sin,
                            const float* __restrict__ pos_cos)
{
    int idx = blockIdx.x * 256 + threadIdx.x;     // over NH*NTOK*32 pairs
    if (idx >= NH * NTOK * 32) return;
    int dp  = idx & 31;
    int tok = (idx >> 5) & (NTOK - 1);
    int h   = idx >> 19;                          // NTOK*32 = 2^19
    int d0  = dp * 2;
    const float* base = g_qkv + (size_t)tok * QKVW + h * DH + d0;
    float2 qv = *(const float2*)(base);
    float2 kv = *(const float2*)(base + HID);
    float2 vv = *(const float2*)(base + 2 * HID);
    float2 sv = *(const float2*)(pos_sin + (size_t)tok * DH + d0);
    float2 cv = *(const float2*)(pos_cos + (size_t)tok * DH + d0);
    size_t o = ((size_t)h * NTOK + tok) * DH + d0;
    float2 qr, kr;
    qr.x = (qv.x * cv.x - qv.y * sv.x) * 0.125f;
    qr.y = (qv.y * cv.y + qv.x * sv.y) * 0.125f;
    kr.x = kv.x * cv.x - kv.y * sv.x;
    kr.y = kv.y * cv.y + kv.x * sv.y;
    *(float2*)(g_qr + o) = make_float2(f2tf32_rna(qr.x), f2tf32_rna(qr.y));
    *(float2*)(g_kr + o) = make_float2(f2tf32_rna(kr.x), f2tf32_rna(kr.y));
    *(float2*)(g_vr + o) = make_float2(f2tf32_rna(vv.x), f2tf32_rna(vv.y));
}

// ---------------------------------------------------------------- HMMA tf32 GEMM (unchanged from R10)
__global__ __launch_bounds__(128, 2)
void tgemm_kernel(const float* __restrict__ A, int lda,
                  const float* __restrict__ Bt, int ldb,
                  const float* __restrict__ bias,
                  const float* __restrict__ R,
                  float* __restrict__ C, int ldc,
                  int K, int epi)
{
    extern __shared__ float sm[];
    uint32_t sbase = smem_u32(sm);

    int t = threadIdx.x;
    int wid = t >> 5, lane = t & 31;
    int warp_m = (wid >> 1) * 64, warp_n = (wid & 1) * 64;
    int bm = blockIdx.y * 128, bn = blockIdx.x * 128;
    int r = lane >> 2, c = lane & 3;

    const float* Ag = A  + (size_t)bm * lda;
    const float* Bg = Bt + (size_t)bn * ldb;

    float acc[32][4];
    #pragma unroll
    for (int i = 0; i < 32; i++)
        #pragma unroll
        for (int j = 0; j < 4; j++) acc[i][j] = 0.f;

    int cm[8], ck[8];
    #pragma unroll
    for (int i = 0; i < 8; i++) {
        int id = t + i * 128;
        cm[i] = id >> 3;
        ck[i] = (id & 7) * 4;
    }

    auto load_stage = [&](int buf, int kbase) {
        uint32_t ab = sbase + (uint32_t)buf * STAGE_BYTES;
        uint32_t bb = ab + TILE_BYTES;
        #pragma unroll
        for (int i = 0; i < 8; i++) {
            cp_async16(ab + (uint32_t)(cm[i] * ASTR + ck[i]) * 4u,
                       Ag + (size_t)cm[i] * lda + kbase + ck[i]);
            cp_async16(bb + (uint32_t)(cm[i] * ASTR + ck[i]) * 4u,
                       Bg + (size_t)cm[i] * ldb + kbase + ck[i]);
        }
    };

    int S = K / 32;
    load_stage(0, 0);
    cp_commit();

    for (int s = 0; s < S; s++) {
        cp_wait0();
        __syncthreads();
        if (s + 1 < S) {
            load_stage((s + 1) & 1, (s + 1) * 32);
            cp_commit();
        }

        uint32_t ab = sbase + (uint32_t)(s & 1) * STAGE_BYTES;
        uint32_t bb = ab + TILE_BYTES;
        #pragma unroll
        for (int ks = 0; ks < 4; ks++) {
            int k0 = ks * 8;
            uint32_t af[4][4];
            #pragma unroll
            for (int mt = 0; mt < 4; mt++) {
                uint32_t base = ab + (uint32_t)((warp_m + mt * 16 + r) * ASTR + k0 + c) * 4u;
                af[mt][0] = lds32(base);
                af[mt][1] = lds32(base + 8u * ASTR * 4u);
                af[mt][2] = lds32(base + 16u);
                af[mt][3] = lds32(base + 8u * ASTR * 4u + 16u);
            }
            uint32_t bf[8][2];
            #pragma unroll
            for (int nt = 0; nt < 8; nt++) {
                uint32_t base = bb + (uint32_t)((warp_n + nt * 8 + r) * ASTR + k0 + c) * 4u;
                bf[nt][0] = lds32(base);
                bf[nt][1] = lds32(base + 16u);
            }
            #pragma unroll
            for (int mt = 0; mt < 4; mt++)
                #pragma unroll
                for (int nt = 0; nt < 8; nt++)
                    mma_tf32(acc[mt * 8 + nt], af[mt], bf[nt]);
        }
    }

    #pragma unroll
    for (int mt = 0; mt < 4; mt++) {
        #pragma unroll
        for (int nt = 0; nt < 8; nt++) {
            float* a4 = acc[mt * 8 + nt];
            int gm0 = bm + warp_m + mt * 16 + r;
            int gn  = bn + warp_n + nt * 8 + c * 2;
            float bx = bias[gn], by = bias[gn + 1];
            #pragma unroll
            for (int half = 0; half < 2; half++) {
                int gm = gm0 + half * 8;
                float vx = a4[half * 2 + 0] + bx;
                float vy = a4[half * 2 + 1] + by;
                if (R) {
                    const float* rp = R + (size_t)gm * ldc + gn;
                    vx += rp[0]; vy += rp[1];
                }
                if (epi == 1) { vx = gelu_f(vx); vy = gelu_f(vy); }
                *(float2*)(C + (size_t)gm * ldc + gn) = make_float2(vx, vy);
            }
        }
    }
}

// ---------------------------------------------------------------- Attention (flash, mma.sync tf32)
// Block: 128 queries x 1 head, 8 warps (16 queries each). Keys tiled by 32.
// Fragment mappings identical to the validated tgemm patterns.
__global__ __launch_bounds__(256, 2)
void attn_kernel(const int* __restrict__ lenp)
{
    extern __shared__ float sma[];
    float* Qs = sma;                 // [128][AQ], reused as Ps after Q-frag extraction
    float* Ks = sma + 128 * AQ;      // [32][AQ]
    float* Vs = Ks + 32 * AQ;        // [32][AQ]  (natural [key][dim])
    float* Ps = Qs;                  // per-warp [16][PSTR]

    int blk = blockIdx.x, h = blockIdx.y;
    int t = threadIdx.x, wid = t >> 5, lane = t & 31;
    int r = lane >> 2, cc = lane & 3;
    int q0  = blk * 128;
    int q0w = q0 + wid * 16;
    unsigned lm = ~((unsigned)(*lenp) - 1u);
    int qlo = q0w + r, qhi = qlo + 8;
    unsigned seqlo = (unsigned)qlo & lm, seqhi = (unsigned)qhi & lm;

    const float* Qg = g_qr + ((size_t)h * NTOK + q0) * DH;
    const float* Kg = g_kr + (size_t)h * NTOK * DH;
    const float* Vg = g_vr + (size_t)h * NTOK * DH;

    // load Q tile 128x64 into Qs
    #pragma unroll
    for (int i = 0; i < 8; i++) {
        int f = t + i * 256;          // 2048 float4
        int row = f >> 4, c4 = f & 15;
        *(float4*)&Qs[row * AQ + c4 * 4] = *(const float4*)(Qg + (size_t)row * DH + c4 * 4);
    }
    __syncthreads();

    // extract Q fragments (A-operand), kept in registers for the whole block
    uint32_t qf[8][4];
    #pragma unroll
    for (int ks = 0; ks < 8; ks++) {
        const float* base = &Qs[(wid * 16 + r) * AQ + ks * 8 + cc];
        qf[ks][0] = __float_as_uint(base[0]);
        qf[ks][1] = __float_as_uint(base[8 * AQ]);
        qf[ks][2] = __float_as_uint(base[4]);
        qf[ks][3] = __float_as_uint(base[8 * AQ + 4]);
    }

    float o[8][4];
    #pragma unroll
    for (int i = 0; i < 8; i++)
        #pragma unroll
        for (int j = 0; j < 4; j++) o[i][j] = 0.f;
    float m_lo = -1e30f, m_hi = -1e30f, l_lo = 0.f, l_hi = 0.f;

    int kt0 = (q0 < 256) ? ((256 - q0) >> 5) : 0;

    for (int kt = kt0; kt < 12; kt++) {
        int kbase = q0 - 256 + kt * 32;
        __syncthreads();              // previous tile fully consumed (also covers Q-frag reads)
        #pragma unroll
        for (int i = 0; i < 2; i++) {
            int f = t + i * 256;      // 512 float4 per array
            int row = f >> 4, c4 = f & 15;
            *(float4*)&Ks[row * AQ + c4 * 4] = *(const float4*)(Kg + (size_t)(kbase + row) * DH + c4 * 4);
            *(float4*)&Vs[row * AQ + c4 * 4] = *(const float4*)(Vg + (size_t)(kbase + row) * DH + c4 * 4);
        }
        __syncthreads();

        bool active = (kbase <= q0w + 15) && (q0w - (kbase + 31) < WIN);
        if (active) {
            // scores: S[16 x 32] = Q @ K^T
            float sc[4][4];
            #pragma unroll
            for (int nt = 0; nt < 4; nt++) {
                sc[nt][0] = sc[nt][1] = sc[nt][2] = sc[nt][3] = 0.f;
                #pragma unroll
                for (int ks = 0; ks < 8; ks++) {
                    const float* bb = &Ks[(nt * 8 + r) * AQ + ks * 8 + cc];
                    uint32_t bf[2] = { __float_as_uint(bb[0]), __float_as_uint(bb[4]) };
                    mma_tf32(sc[nt], qf[ks], bf);
                }
            }
            // mask + online softmax (C layout: c0=(r,2c) c1=(r,2c+1) c2=(r+8,2c) c3=(r+8,2c+1))
            float tlo = -1e30f, thi = -1e30f;
            #pragma unroll
            for (int nt = 0; nt < 4; nt++) {
                #pragma unroll
                for (int b = 0; b < 2; b++) {
                    int ktok = kbase + nt * 8 + 2 * cc + b;
                    unsigned kseq = (unsigned)ktok & lm;
                    int dlo = qlo - ktok, dhi = qhi - ktok;
                    if (!(dlo >= 0 && dlo < WIN && kseq == seqlo)) sc[nt][b]     = -2e30f;
                    if (!(dhi >= 0 && dhi < WIN && kseq == seqhi)) sc[nt][2 + b] = -2e30f;
                    tlo = fmaxf(tlo, sc[nt][b]);
                    thi = fmaxf(thi, sc[nt][2 + b]);
                }
            }
            tlo = fmaxf(tlo, __shfl_xor_sync(0xffffffffu, tlo, 1));
            tlo = fmaxf(tlo, __shfl_xor_sync(0xffffffffu, tlo, 2));
            thi = fmaxf(thi, __shfl_xor_sync(0xffffffffu, thi, 1));
            thi = fmaxf(thi, __shfl_xor_sync(0xffffffffu, thi, 2));

            float mn_lo = fmaxf(m_lo, tlo), mn_hi = fmaxf(m_hi, thi);
            float co_lo = __expf(m_lo - mn_lo), co_hi = __expf(m_hi - mn_hi);
            m_lo = mn_lo; m_hi = mn_hi;
            l_lo *= co_lo; l_hi *= co_hi;
            #pragma unroll
            for (int i = 0; i < 8; i++) {
                o[i][0] *= co_lo; o[i][1] *= co_lo;
                o[i][2] *= co_hi; o[i][3] *= co_hi;
            }
            float* Pw = Ps + wid * 16 * PSTR;
            #pragma unroll
            for (int nt = 0; nt < 4; nt++) {
                float p0 = f2tf32_rna(__expf(sc[nt][0] - mn_lo));
                float p1 = f2tf32_rna(__expf(sc[nt][1] - mn_lo));
                float p2 = f2tf32_rna(__expf(sc[nt][2] - mn_hi));
                float p3 = f2tf32_rna(__expf(sc[nt][3] - mn_hi));
                l_lo += p0 + p1; l_hi += p2 + p3;
                Pw[r * PSTR + nt * 8 + 2 * cc]           = p0;
                Pw[r * PSTR + nt * 8 + 2 * cc + 1]       = p1;
                Pw[(r + 8) * PSTR + nt * 8 + 2 * cc]     = p2;
                Pw[(r + 8) * PSTR + nt * 8 + 2 * cc + 1] = p3;
            }
            __syncwarp();
            // P fragments (A-operand, K=32 in 4 steps)
            uint32_t pf[4][4];
            #pragma unroll
            for (int kk = 0; kk < 4; kk++) {
                const float* base = &Pw[r * PSTR + kk * 8 + cc];
                pf[kk][0] = __float_as_uint(base[0]);
                pf[kk][1] = __float_as_uint(base[8 * PSTR]);
                pf[kk][2] = __float_as_uint(base[4]);
                pf[kk][3] = __float_as_uint(base[8 * PSTR + 4]);
            }
            // O += P @ V  (B-frag read transposed from natural Vs[key][dim])
            #pragma unroll
            for (int ntd = 0; ntd < 8; ntd++) {
                #pragma unroll
                for (int kk = 0; kk < 4; kk++) {
                    uint32_t bf[2] = {
                        __float_as_uint(Vs[(kk * 8 + cc) * AQ + ntd * 8 + r]),
                        __float_as_uint(Vs[(kk * 8 + cc + 4) * AQ + ntd * 8 + r]) };
                    mma_tf32(o[ntd], pf[kk], bf);
                }
            }
        }
    }

    // reduce l across the 4-lane row group, divide, store
    l_lo += __shfl_xor_sync(0xffffffffu, l_lo, 1);
    l_lo += __shfl_xor_sync(0xffffffffu, l_lo, 2);
    l_hi += __shfl_xor_sync(0xffffffffu, l_hi, 1);
    l_hi += __shfl_xor_sync(0xffffffffu, l_hi, 2);
    float ilo = 1.0f / l_lo, ihi = 1.0f / l_hi;
    float* out_lo = g_comb + (size_t)qlo * COMBW + h * DH;
    float* out_hi = g_comb + (size_t)qhi * COMBW + h * DH;
    #pragma unroll
    for (int ntd = 0; ntd < 8; ntd++) {
        int gn = ntd * 8 + 2 * cc;
        *(float2*)(out_lo + gn) = make_float2(o[ntd][0] * ilo, o[ntd][1] * ilo);
        *(float2*)(out_hi + gn) = make_float2(o[ntd][2] * ihi, o[ntd][3] * ihi);
    }
}

// ---------------------------------------------------------------- launch
extern "C" void kernel_launch(void* const* d_in, const int* in_sizes, int n_in,
                              void* d_out, int out_size)
{
    (void)in_sizes; (void)n_in; (void)out_size;
    const float* x        = (const float*)d_in[0];
    const float* pos_sin  = (const float*)d_in[2];
    const float* pos_cos  = (const float*)d_in[3];
    const float* ln_scale = (const float*)d_in[4];
    const float* ln_off   = (const float*)d_in[5];
    const float* w_in     = (const float*)d_in[6];
    const float* b_in     = (const float*)d_in[7];
    const float* w_out    = (const float*)d_in[8];
    const float* b_out    = (const float*)d_in[9];
    const int*   lenp     = (const int*)d_in[10];
    float* out = (float*)d_out;

    static float *p_xn = nullptr, *p_qkv = nullptr, *p_comb = nullptr,
                 *p_wt1 = nullptr, *p_wt2 = nullptr;
    static cudaStream_t s1 = nullptr;
    static cudaEvent_t e0 = nullptr, eT = nullptr, eLN = nullptr, eF = nullptr;
    if (!p_xn) {
        cudaGetSymbolAddress((void**)&p_xn,   g_xn);
        cudaGetSymbolAddress((void**)&p_qkv,  g_qkv);
        cudaGetSymbolAddress((void**)&p_comb, g_comb);
        cudaGetSymbolAddress((void**)&p_wt1,  g_wt1);
        cudaGetSymbolAddress((void**)&p_wt2,  g_wt2);
        cudaFuncSetAttribute(tgemm_kernel,
                             cudaFuncAttributeMaxDynamicSharedMemorySize, DSMEM_BYTES);
        cudaFuncSetAttribute(attn_kernel,
                             cudaFuncAttributeMaxDynamicSharedMemorySize, ATTN_SMEM);
        cudaStreamCreateWithFlags(&s1, cudaStreamNonBlocking);
        cudaEventCreateWithFlags(&e0,  cudaEventDisableTiming);
        cudaEventCreateWithFlags(&eT,  cudaEventDisableTiming);
        cudaEventCreateWithFlags(&eLN, cudaEventDisableTiming);
        cudaEventCreateWithFlags(&eF,  cudaEventDisableTiming);
    }

    // fork s1 from the (captured) default stream
    cudaEventRecord(e0, 0);
    cudaStreamWaitEvent(s1, e0, 0);

    // s1: weight transposes (+tf32 round); s0: layernorm
    transpose_kernel<<<dim3(MIDW / 32, HID / 32),   dim3(32, 8), 0, s1>>>(w_in,  p_wt1, HID,   MIDW);
    transpose_kernel<<<dim3(HID / 32,  COMBW / 32), dim3(32, 8), 0, s1>>>(w_out, p_wt2, COMBW, HID);
    ln_kernel<<<NTOK, 256>>>(x, ln_scale, ln_off);
    cudaEventRecord(eLN, 0);

    // s0: QKV GEMM (needs wt1 from s1)
    cudaEventRecord(eT, s1);
    cudaStreamWaitEvent(0, eT, 0);
    tgemm_kernel<<<dim3(QKVW / 128, NTOK / 128), 128, DSMEM_BYTES>>>(
        p_xn, HID, p_wt1, HID, b_in, nullptr, p_qkv, QKVW, HID, 0);

    // s1: FF GEMM + gelu (needs ln) — overlaps QKV + rope + attn
    cudaStreamWaitEvent(s1, eLN, 0);
    tgemm_kernel<<<dim3(INTER / 128, NTOK / 128), 128, DSMEM_BYTES, s1>>>(
        p_xn, HID, p_wt1 + (size_t)QKVW * HID, HID, b_in + QKVW, nullptr,
        p_comb + HID, COMBW, HID, 1);
    cudaEventRecord(eF, s1);

    // s0: RoPE precompute, then flash attention -> comb[:, :768]
    rope_kernel<<<(NH * NTOK * 32) / 256, 256>>>(pos_sin, pos_cos);
    attn_kernel<<<dim3(NTOK / 128, NH), 256, ATTN_SMEM>>>(lenp);

    // join, then s0: out = xn + comb @ w_out + b_out
    cudaStreamWaitEvent(0, eF, 0);
    tgemm_kernel<<<dim3(HID / 128, NTOK / 128), 128, DSMEM_BYTES>>>(
        p_comb, COMBW, p_wt2, COMBW, b_out, p_xn, out, HID, COMBW, 0);
}

// round 12
// speedup vs baseline: 3.2573x; 1.0065x over previous
#include <cuda_runtime.h>
#include <cfloat>
#include <cstddef>
#include <cstdint>

#define HID   768
#define INTER 3072
#define NH    12
#define DH    64
#define NTOK  16384
#define WIN   256
#define CH    256
#define MIDW  (3*HID + INTER)   // 5376
#define QKVW  (3*HID)           // 2304
#define COMBW (HID + INTER)     // 3840
#define NCHUNK (NTOK / CH)      // 64

#define ASTR 36                       // gemm smem row stride in floats (pad 4)
#define TILE_BYTES (128 * ASTR * 4)   // 18432 per operand tile
#define STAGE_BYTES (2 * TILE_BYTES)  // A + B = 36864
#define GSTAGES 3
#define DSMEM_BYTES (GSTAGES * STAGE_BYTES) // 110592; 2 CTAs/SM = 216 KB

#define AQ   68                       // attn Q/K/V smem row stride (floats)
#define PSTR 36                       // attn probs smem row stride
#define ATTN_SMEM ((128*AQ + 32*AQ + 32*AQ) * 4)   // 52224 B

// Scratch (device globals: allocation inside kernel_launch is forbidden)
__device__ float g_xn  [(size_t)NTOK * HID];     //  50 MB
__device__ float g_qkv [(size_t)NTOK * QKVW];    // 151 MB
__device__ float g_comb[(size_t)NTOK * COMBW];   // 252 MB
__device__ float g_wt1 [(size_t)MIDW * HID];     //  16.5 MB
__device__ float g_wt2 [(size_t)HID * COMBW];    //  11.8 MB
__device__ float g_qr  [(size_t)NH * NTOK * DH]; //  50 MB  RoPE'd+scaled Q [h][tok][d]
__device__ float g_kr  [(size_t)NH * NTOK * DH]; //  50 MB  RoPE'd K
__device__ float g_vr  [(size_t)NH * NTOK * DH]; //  50 MB  V

// ---------------------------------------------------------------- helpers
__device__ __forceinline__ uint32_t smem_u32(const void* p) {
    uint32_t a;
    asm("{ .reg .u64 t; cvta.to.shared.u64 t, %1; cvt.u32.u64 %0, t; }"
        : "=r"(a) : "l"(p));
    return a;
}
__device__ __forceinline__ float f2tf32_rna(float x) {
    uint32_t u;
    asm("cvt.rna.tf32.f32 %0, %1;" : "=r"(u) : "f"(x));
    return __uint_as_float(u);
}
__device__ __forceinline__ void cp_async16(uint32_t dst, const void* src) {
    asm volatile("cp.async.cg.shared.global [%0], [%1], 16;"
                 :: "r"(dst), "l"(src) : "memory");
}
__device__ __forceinline__ void cp_commit() {
    asm volatile("cp.async.commit_group;" ::: "memory");
}
__device__ __forceinline__ void cp_wait1() {
    asm volatile("cp.async.wait_group 1;" ::: "memory");
}
__device__ __forceinline__ void cp_wait0() {
    asm volatile("cp.async.wait_group 0;" ::: "memory");
}
__device__ __forceinline__ uint32_t lds32(uint32_t addr) {
    uint32_t v;
    asm volatile("ld.shared.b32 %0, [%1];" : "=r"(v) : "r"(addr));
    return v;
}
__device__ __forceinline__ void mma_tf32(float* d, const uint32_t* a, const uint32_t* b) {
    asm volatile(
        "mma.sync.aligned.m16n8k8.row.col.f32.tf32.tf32.f32 "
        "{%0,%1,%2,%3}, {%4,%5,%6,%7}, {%8,%9}, {%0,%1,%2,%3};"
        : "+f"(d[0]), "+f"(d[1]), "+f"(d[2]), "+f"(d[3])
        : "r"(a[0]), "r"(a[1]), "r"(a[2]), "r"(a[3]), "r"(b[0]), "r"(b[1]));
}

// ---------------------------------------------------------------- GELU (tanh approx = jax default)
__device__ __forceinline__ float gelu_f(float x) {
    float x3 = x * x * x;
    return 0.5f * x * (1.0f + tanhf(0.7978845608028654f * (x + 0.044715f * x3)));
}

// ---------------------------------------------------------------- LayerNorm
__global__ void ln_kernel(const float* __restrict__ x,
                          const float* __restrict__ gam,
                          const float* __restrict__ bet)
{
    int row = blockIdx.x;
    int t   = threadIdx.x;
    const float* xr = x + (size_t)row * HID;
    float v0 = xr[t], v1 = xr[t + 256], v2 = xr[t + 512];
    float s  = v0 + v1 + v2;
    float s2 = v0*v0 + v1*v1 + v2*v2;
    #pragma unroll
    for (int o = 16; o > 0; o >>= 1) {
        s  += __shfl_xor_sync(0xffffffffu, s,  o);
        s2 += __shfl_xor_sync(0xffffffffu, s2, o);
    }
    __shared__ float red0[8], red1[8];
    __shared__ float stat[2];
    int w = t >> 5, l = t & 31;
    if (l == 0) { red0[w] = s; red1[w] = s2; }
    __syncthreads();
    if (t == 0) {
        float ts = 0.f, ts2 = 0.f;
        #pragma unroll
        for (int i = 0; i < 8; i++) { ts += red0[i]; ts2 += red1[i]; }
        float mu  = ts * (1.0f / HID);
        float var = ts2 * (1.0f / HID) - mu * mu;
        stat[0] = mu;
        stat[1] = rsqrtf(var + 1e-5f);
    }
    __syncthreads();
    float mu = stat[0], inv = stat[1];
    float* o = g_xn + (size_t)row * HID;
    o[t]       = (v0 - mu) * inv * gam[t]       + bet[t];
    o[t + 256] = (v1 - mu) * inv * gam[t + 256] + bet[t + 256];
    o[t + 512] = (v2 - mu) * inv * gam[t + 512] + bet[t + 512];
}

// ---------------------------------------------------------------- Transpose (R x C -> C x R), dims % 32 == 0
__global__ void transpose_kernel(const float* __restrict__ in, float* __restrict__ out,
                                 int R, int C)
{
    __shared__ float tile[32][33];
    int bx = blockIdx.x * 32, by = blockIdx.y * 32;
    int tx = threadIdx.x, ty = threadIdx.y;
    #pragma unroll
    for (int i = 0; i < 32; i += 8)
        tile[ty + i][tx] = in[(size_t)(by + ty + i) * C + bx + tx];
    __syncthreads();
    #pragma unroll
    for (int i = 0; i < 32; i += 8)
        out[(size_t)(bx + ty + i) * R + by + tx] = f2tf32_rna(tile[tx][ty + i]);
}

// ---------------------------------------------------------------- RoPE precompute
__global__ void rope_kernel(const float* __restrict__ pos_sin,
                            const float* __restrict__ pos_cos)
{
    int idx = blockIdx.x * 256 + threadIdx.x;     // over NH*NTOK*32 pairs
    if (idx >= NH * NTOK * 32) return;
    int dp  = idx & 31;
    int tok = (idx >> 5) & (NTOK - 1);
    int h   = idx >> 19;                          // NTOK*32 = 2^19
    int d0  = dp * 2;
    const float* base = g_qkv + (size_t)tok * QKVW + h * DH + d0;
    float2 qv = *(const float2*)(base);
    float2 kv = *(const float2*)(base + HID);
    float2 vv = *(const float2*)(base + 2 * HID);
    float2 sv = *(const float2*)(pos_sin + (size_t)tok * DH + d0);
    float2 cv = *(const float2*)(pos_cos + (size_t)tok * DH + d0);
    size_t o = ((size_t)h * NTOK + tok) * DH + d0;
    float2 qr, kr;
    qr.x = (qv.x * cv.x - qv.y * sv.x) * 0.125f;
    qr.y = (qv.y * cv.y + qv.x * sv.y) * 0.125f;
    kr.x = kv.x * cv.x - kv.y * sv.x;
    kr.y = kv.y * cv.y + kv.x * sv.y;
    *(float2*)(g_qr + o) = make_float2(f2tf32_rna(qr.x), f2tf32_rna(qr.y));
    *(float2*)(g_kr + o) = make_float2(f2tf32_rna(kr.x), f2tf32_rna(kr.y));
    *(float2*)(g_vr + o) = make_float2(f2tf32_rna(vv.x), f2tf32_rna(vv.y));
}

// ---------------------------------------------------------------- HMMA tf32 GEMM
// 128x128 CTA tile, 4 warps, 64x64 warp tile. 3-stage cp.async ring:
// prefetch distance 2 covers DRAM latency (the R8-R10 tensor=54% plateau
// was the uncovered latency tail of a 1-stage-ahead prefetch).
__global__ __launch_bounds__(128, 2)
void tgemm_kernel(const float* __restrict__ A, int lda,
                  const float* __restrict__ Bt, int ldb,
                  const float* __restrict__ bias,
                  const float* __restrict__ R,
                  float* __restrict__ C, int ldc,
                  int K, int epi)
{
    extern __shared__ float sm[];
    uint32_t sbase = smem_u32(sm);

    int t = threadIdx.x;
    int wid = t >> 5, lane = t & 31;
    int warp_m = (wid >> 1) * 64, warp_n = (wid & 1) * 64;
    int bm = blockIdx.y * 128, bn = blockIdx.x * 128;
    int r = lane >> 2, c = lane & 3;

    const float* Ag = A  + (size_t)bm * lda;
    const float* Bg = Bt + (size_t)bn * ldb;

    float acc[32][4];
    #pragma unroll
    for (int i = 0; i < 32; i++)
        #pragma unroll
        for (int j = 0; j < 4; j++) acc[i][j] = 0.f;

    int cm[8], ck[8];
    #pragma unroll
    for (int i = 0; i < 8; i++) {
        int id = t + i * 128;
        cm[i] = id >> 3;
        ck[i] = (id & 7) * 4;
    }

    auto load_stage = [&](int buf, int kbase) {
        uint32_t ab = sbase + (uint32_t)buf * STAGE_BYTES;
        uint32_t bb = ab + TILE_BYTES;
        #pragma unroll
        for (int i = 0; i < 8; i++) {
            cp_async16(ab + (uint32_t)(cm[i] * ASTR + ck[i]) * 4u,
                       Ag + (size_t)cm[i] * lda + kbase + ck[i]);
            cp_async16(bb + (uint32_t)(cm[i] * ASTR + ck[i]) * 4u,
                       Bg + (size_t)cm[i] * ldb + kbase + ck[i]);
        }
    };

    int S = K / 32;
    // preload stages 0 and 1 (S >= 2 at every call site: min K = 768)
    load_stage(0, 0);
    cp_commit();
    load_stage(1, 32);
    cp_commit();

    int buf = 0;
    for (int s = 0; s < S; s++) {
        if (s + 1 < S) cp_wait1();   // oldest pending group (stage s) done
        else           cp_wait0();
        __syncthreads();             // + everyone finished reading buf(s-1)
        int nxt = s + 2;
        if (nxt < S) {
            int nbuf = buf + 2; if (nbuf >= GSTAGES) nbuf -= GSTAGES;
            load_stage(nbuf, nxt * 32);
            cp_commit();
        }

        uint32_t ab = sbase + (uint32_t)buf * STAGE_BYTES;
        uint32_t bb = ab + TILE_BYTES;
        #pragma unroll
        for (int ks = 0; ks < 4; ks++) {
            int k0 = ks * 8;
            uint32_t af[4][4];
            #pragma unroll
            for (int mt = 0; mt < 4; mt++) {
                uint32_t base = ab + (uint32_t)((warp_m + mt * 16 + r) * ASTR + k0 + c) * 4u;
                af[mt][0] = lds32(base);
                af[mt][1] = lds32(base + 8u * ASTR * 4u);
                af[mt][2] = lds32(base + 16u);
                af[mt][3] = lds32(base + 8u * ASTR * 4u + 16u);
            }
            uint32_t bf[8][2];
            #pragma unroll
            for (int nt = 0; nt < 8; nt++) {
                uint32_t base = bb + (uint32_t)((warp_n + nt * 8 + r) * ASTR + k0 + c) * 4u;
                bf[nt][0] = lds32(base);
                bf[nt][1] = lds32(base + 16u);
            }
            #pragma unroll
            for (int mt = 0; mt < 4; mt++)
                #pragma unroll
                for (int nt = 0; nt < 8; nt++)
                    mma_tf32(acc[mt * 8 + nt], af[mt], bf[nt]);
        }
        if (++buf == GSTAGES) buf = 0;
    }

    #pragma unroll
    for (int mt = 0; mt < 4; mt++) {
        #pragma unroll
        for (int nt = 0; nt < 8; nt++) {
            float* a4 = acc[mt * 8 + nt];
            int gm0 = bm + warp_m + mt * 16 + r;
            int gn  = bn + warp_n + nt * 8 + c * 2;
            float bx = bias[gn], by = bias[gn + 1];
            #pragma unroll
            for (int half = 0; half < 2; half++) {
                int gm = gm0 + half * 8;
                float vx = a4[half * 2 + 0] + bx;
                float vy = a4[half * 2 + 1] + by;
                if (R) {
                    const float* rp = R + (size_t)gm * ldc + gn;
                    vx += rp[0]; vy += rp[1];
                }
                if (epi == 1) { vx = gelu_f(vx); vy = gelu_f(vy); }
                *(float2*)(C + (size_t)gm * ldc + gn) = make_float2(vx, vy);
            }
        }
    }
}

// ---------------------------------------------------------------- Attention (flash, mma.sync tf32; unchanged from R11)
__global__ __launch_bounds__(256, 2)
void attn_kernel(const int* __restrict__ lenp)
{
    extern __shared__ float sma[];
    float* Qs = sma;
    float* Ks = sma + 128 * AQ;
    float* Vs = Ks + 32 * AQ;
    float* Ps = Qs;

    int blk = blockIdx.x, h = blockIdx.y;
    int t = threadIdx.x, wid = t >> 5, lane = t & 31;
    int r = lane >> 2, cc = lane & 3;
    int q0  = blk * 128;
    int q0w = q0 + wid * 16;
    unsigned lm = ~((unsigned)(*lenp) - 1u);
    int qlo = q0w + r, qhi = qlo + 8;
    unsigned seqlo = (unsigned)qlo & lm, seqhi = (unsigned)qhi & lm;

    const float* Qg = g_qr + ((size_t)h * NTOK + q0) * DH;
    const float* Kg = g_kr + (size_t)h * NTOK * DH;
    const float* Vg = g_vr + (size_t)h * NTOK * DH;

    #pragma unroll
    for (int i = 0; i < 8; i++) {
        int f = t + i * 256;
        int row = f >> 4, c4 = f & 15;
        *(float4*)&Qs[row * AQ + c4 * 4] = *(const float4*)(Qg + (size_t)row * DH + c4 * 4);
    }
    __syncthreads();

    uint32_t qf[8][4];
    #pragma unroll
    for (int ks = 0; ks < 8; ks++) {
        const float* base = &Qs[(wid * 16 + r) * AQ + ks * 8 + cc];
        qf[ks][0] = __float_as_uint(base[0]);
        qf[ks][1] = __float_as_uint(base[8 * AQ]);
        qf[ks][2] = __float_as_uint(base[4]);
        qf[ks][3] = __float_as_uint(base[8 * AQ + 4]);
    }

    float o[8][4];
    #pragma unroll
    for (int i = 0; i < 8; i++)
        #pragma unroll
        for (int j = 0; j < 4; j++) o[i][j] = 0.f;
    float m_lo = -1e30f, m_hi = -1e30f, l_lo = 0.f, l_hi = 0.f;

    int kt0 = (q0 < 256) ? ((256 - q0) >> 5) : 0;

    for (int kt = kt0; kt < 12; kt++) {
        int kbase = q0 - 256 + kt * 32;
        __syncthreads();
        #pragma unroll
        for (int i = 0; i < 2; i++) {
            int f = t + i * 256;
            int row = f >> 4, c4 = f & 15;
            *(float4*)&Ks[row * AQ + c4 * 4] = *(const float4*)(Kg + (size_t)(kbase + row) * DH + c4 * 4);
            *(float4*)&Vs[row * AQ + c4 * 4] = *(const float4*)(Vg + (size_t)(kbase + row) * DH + c4 * 4);
        }
        __syncthreads();

        bool active = (kbase <= q0w + 15) && (q0w - (kbase + 31) < WIN);
        if (active) {
            float sc[4][4];
            #pragma unroll
            for (int nt = 0; nt < 4; nt++) {
                sc[nt][0] = sc[nt][1] = sc[nt][2] = sc[nt][3] = 0.f;
                #pragma unroll
                for (int ks = 0; ks < 8; ks++) {
                    const float* bb = &Ks[(nt * 8 + r) * AQ + ks * 8 + cc];
                    uint32_t bf[2] = { __float_as_uint(bb[0]), __float_as_uint(bb[4]) };
                    mma_tf32(sc[nt], qf[ks], bf);
                }
            }
            float tlo = -1e30f, thi = -1e30f;
            #pragma unroll
            for (int nt = 0; nt < 4; nt++) {
                #pragma unroll
                for (int b = 0; b < 2; b++) {
                    int ktok = kbase + nt * 8 + 2 * cc + b;
                    unsigned kseq = (unsigned)ktok & lm;
                    int dlo = qlo - ktok, dhi = qhi - ktok;
                    if (!(dlo >= 0 && dlo < WIN && kseq == seqlo)) sc[nt][b]     = -2e30f;
                    if (!(dhi >= 0 && dhi < WIN && kseq == seqhi)) sc[nt][2 + b] = -2e30f;
                    tlo = fmaxf(tlo, sc[nt][b]);
                    thi = fmaxf(thi, sc[nt][2 + b]);
                }
            }
            tlo = fmaxf(tlo, __shfl_xor_sync(0xffffffffu, tlo, 1));
            tlo = fmaxf(tlo, __shfl_xor_sync(0xffffffffu, tlo, 2));
            thi = fmaxf(thi, __shfl_xor_sync(0xffffffffu, thi, 1));
            thi = fmaxf(thi, __shfl_xor_sync(0xffffffffu, thi, 2));

            float mn_lo = fmaxf(m_lo, tlo), mn_hi = fmaxf(m_hi, thi);
            float co_lo = __expf(m_lo - mn_lo), co_hi = __expf(m_hi - mn_hi);
            m_lo = mn_lo; m_hi = mn_hi;
            l_lo *= co_lo; l_hi *= co_hi;
            #pragma unroll
            for (int i = 0; i < 8; i++) {
                o[i][0] *= co_lo; o[i][1] *= co_lo;
                o[i][2] *= co_hi; o[i][3] *= co_hi;
            }
            float* Pw = Ps + wid * 16 * PSTR;
            #pragma unroll
            for (int nt = 0; nt < 4; nt++) {
                float p0 = f2tf32_rna(__expf(sc[nt][0] - mn_lo));
                float p1 = f2tf32_rna(__expf(sc[nt][1] - mn_lo));
                float p2 = f2tf32_rna(__expf(sc[nt][2] - mn_hi));
                float p3 = f2tf32_rna(__expf(sc[nt][3] - mn_hi));
                l_lo += p0 + p1; l_hi += p2 + p3;
                Pw[r * PSTR + nt * 8 + 2 * cc]           = p0;
                Pw[r * PSTR + nt * 8 + 2 * cc + 1]       = p1;
                Pw[(r + 8) * PSTR + nt * 8 + 2 * cc]     = p2;
                Pw[(r + 8) * PSTR + nt * 8 + 2 * cc + 1] = p3;
            }
            __syncwarp();
            uint32_t pf[4][4];
            #pragma unroll
            for (int kk = 0; kk < 4; kk++) {
                const float* base = &Pw[r * PSTR + kk * 8 + cc];
                pf[kk][0] = __float_as_uint(base[0]);
                pf[kk][1] = __float_as_uint(base[8 * PSTR]);
                pf[kk][2] = __float_as_uint(base[4]);
                pf[kk][3] = __float_as_uint(base[8 * PSTR + 4]);
            }
            #pragma unroll
            for (int ntd = 0; ntd < 8; ntd++) {
                #pragma unroll
                for (int kk = 0; kk < 4; kk++) {
                    uint32_t bf[2] = {
                        __float_as_uint(Vs[(kk * 8 + cc) * AQ + ntd * 8 + r]),
                        __float_as_uint(Vs[(kk * 8 + cc + 4) * AQ + ntd * 8 + r]) };
                    mma_tf32(o[ntd], pf[kk], bf);
                }
            }
        }
    }

    l_lo += __shfl_xor_sync(0xffffffffu, l_lo, 1);
    l_lo += __shfl_xor_sync(0xffffffffu, l_lo, 2);
    l_hi += __shfl_xor_sync(0xffffffffu, l_hi, 1);
    l_hi += __shfl_xor_sync(0xffffffffu, l_hi, 2);
    float ilo = 1.0f / l_lo, ihi = 1.0f / l_hi;
    float* out_lo = g_comb + (size_t)qlo * COMBW + h * DH;
    float* out_hi = g_comb + (size_t)qhi * COMBW + h * DH;
    #pragma unroll
    for (int ntd = 0; ntd < 8; ntd++) {
        int gn = ntd * 8 + 2 * cc;
        *(float2*)(out_lo + gn) = make_float2(o[ntd][0] * ilo, o[ntd][1] * ilo);
        *(float2*)(out_hi + gn) = make_float2(o[ntd][2] * ihi, o[ntd][3] * ihi);
    }
}

// ---------------------------------------------------------------- launch
extern "C" void kernel_launch(void* const* d_in, const int* in_sizes, int n_in,
                              void* d_out, int out_size)
{
    (void)in_sizes; (void)n_in; (void)out_size;
    const float* x        = (const float*)d_in[0];
    const float* pos_sin  = (const float*)d_in[2];
    const float* pos_cos  = (const float*)d_in[3];
    const float* ln_scale = (const float*)d_in[4];
    const float* ln_off   = (const float*)d_in[5];
    const float* w_in     = (const float*)d_in[6];
    const float* b_in     = (const float*)d_in[7];
    const float* w_out    = (const float*)d_in[8];
    const float* b_out    = (const float*)d_in[9];
    const int*   lenp     = (const int*)d_in[10];
    float* out = (float*)d_out;

    static float *p_xn = nullptr, *p_qkv = nullptr, *p_comb = nullptr,
                 *p_wt1 = nullptr, *p_wt2 = nullptr;
    static cudaStream_t s1 = nullptr;
    static cudaEvent_t e0 = nullptr, eT = nullptr, eLN = nullptr, eF = nullptr;
    if (!p_xn) {
        cudaGetSymbolAddress((void**)&p_xn,   g_xn);
        cudaGetSymbolAddress((void**)&p_qkv,  g_qkv);
        cudaGetSymbolAddress((void**)&p_comb, g_comb);
        cudaGetSymbolAddress((void**)&p_wt1,  g_wt1);
        cudaGetSymbolAddress((void**)&p_wt2,  g_wt2);
        cudaFuncSetAttribute(tgemm_kernel,
                             cudaFuncAttributeMaxDynamicSharedMemorySize, DSMEM_BYTES);
        cudaFuncSetAttribute(attn_kernel,
                             cudaFuncAttributeMaxDynamicSharedMemorySize, ATTN_SMEM);
        cudaStreamCreateWithFlags(&s1, cudaStreamNonBlocking);
        cudaEventCreateWithFlags(&e0,  cudaEventDisableTiming);
        cudaEventCreateWithFlags(&eT,  cudaEventDisableTiming);
        cudaEventCreateWithFlags(&eLN, cudaEventDisableTiming);
        cudaEventCreateWithFlags(&eF,  cudaEventDisableTiming);
    }

    // fork s1 from the (captured) default stream
    cudaEventRecord(e0, 0);
    cudaStreamWaitEvent(s1, e0, 0);

    // s1: weight transposes (+tf32 round); s0: layernorm
    transpose_kernel<<<dim3(MIDW / 32, HID / 32),   dim3(32, 8), 0, s1>>>(w_in,  p_wt1, HID,   MIDW);
    transpose_kernel<<<dim3(HID / 32,  COMBW / 32), dim3(32, 8), 0, s1>>>(w_out, p_wt2, COMBW, HID);
    ln_kernel<<<NTOK, 256>>>(x, ln_scale, ln_off);
    cudaEventRecord(eLN, 0);

    // s0: QKV GEMM (needs wt1 from s1)
    cudaEventRecord(eT, s1);
    cudaStreamWaitEvent(0, eT, 0);
    tgemm_kernel<<<dim3(QKVW / 128, NTOK / 128), 128, DSMEM_BYTES>>>(
        p_xn, HID, p_wt1, HID, b_in, nullptr, p_qkv, QKVW, HID, 0);

    // s1: FF GEMM + gelu (needs ln) — overlaps QKV + rope + attn
    cudaStreamWaitEvent(s1, eLN, 0);
    tgemm_kernel<<<dim3(INTER / 128, NTOK / 128), 128, DSMEM_BYTES, s1>>>(
        p_xn, HID, p_wt1 + (size_t)QKVW * HID, HID, b_in + QKVW, nullptr,
        p_comb + HID, COMBW, HID, 1);
    cudaEventRecord(eF, s1);

    // s0: RoPE precompute, then flash attention -> comb[:, :768]
    rope_kernel<<<(NH * NTOK * 32) / 256, 256>>>(pos_sin, pos_cos);
    attn_kernel<<<dim3(NTOK / 128, NH), 256, ATTN_SMEM>>>(lenp);

    // join, then s0: out = xn + comb @ w_out + b_out
    cudaStreamWaitEvent(0, eF, 0);
    tgemm_kernel<<<dim3(HID / 128, NTOK / 128), 128, DSMEM_BYTES>>>(
        p_comb, COMBW, p_wt2, COMBW, b_out, p_xn, out, HID, COMBW, 0);
}